// round 12
// baseline (speedup 1.0000x reference)
#include <cuda_runtime.h>
#include <cuda_bf16.h>
#include <cuda_fp16.h>
#include <math.h>
#include <stdint.h>

#define N_NODES 100000
#define N_EDGES 1600000
#define F_IN 256
#define F_HID 128
#define VOCAB 100000
#define N_SAMP 512

#define SCAN_B 256
#define SCAN_NB ((N_NODES + SCAN_B - 1) / SCAN_B)   // 391

// ---------------- scratch (static __device__ — no allocations) ----------------
__device__ uint32_t g_h16[(size_t)N_NODES * (F_HID / 2)];   // h as half2 pairs, 25.6 MB
__device__ float g_es1[N_NODES];
__device__ float g_ed1[N_NODES];
__device__ int   g_counts[N_NODES];
__device__ int   g_off[N_NODES + 1];
__device__ int   g_cursor[N_NODES];
__device__ int   g_csr_src[N_EDGES];
__device__ float4 g_h2e[N_NODES];           // {h2_0, h2_1, es2, ed2}
__device__ int   g_bsum[SCAN_NB];
__device__ int   g_boff[SCAN_NB];
__device__ __nv_bfloat16 g_Bt_hi[F_HID * F_IN];
__device__ __nv_bfloat16 g_Bt_lo[F_HID * F_IN];
__device__ float g_sw0[N_SAMP];
__device__ float g_sw1[N_SAMP];
__device__ float g_sb[N_SAMP];

// ---------------- s2 branch: zero counts ----------------
__global__ void zero_counts_k() {
    int i = blockIdx.x * blockDim.x + threadIdx.x;
    if (i < N_NODES) g_counts[i] = 0;
}

// ---------------- main branch: W1 split + sample-table gather ----------------
__global__ void prep_k(const float* __restrict__ W1,
                       const int* __restrict__ sample_ids,
                       const float* __restrict__ ssw,
                       const float* __restrict__ ssb) {
    int i = blockIdx.x * blockDim.x + threadIdx.x;
    if (i < F_HID * F_IN) {
        int n = i / F_IN;
        int k = i % F_IN;
        float w = W1[(size_t)k * F_HID + n];
        __nv_bfloat16 hi = __float2bfloat16(w);
        float r = w - __bfloat162float(hi);
        g_Bt_hi[i] = hi;
        g_Bt_lo[i] = __float2bfloat16(r);
    }
    if (i < N_SAMP) {
        int sid = sample_ids[i];
        g_sw0[i] = ssw[2 * sid];
        g_sw1[i] = ssw[2 * sid + 1];
        g_sb[i] = ssb[sid];
    }
}

// ---------------- CSR build (vectorized 2 edges/thread) ----------------
__global__ void hist_k(const int* __restrict__ edge_index) {
    int t = blockIdx.x * blockDim.x + threadIdx.x;
    int e = t * 2;
    if (e < N_EDGES) {
        int2 d = *(const int2*)(edge_index + N_EDGES + e);
        atomicAdd(&g_counts[d.x], 1);
        atomicAdd(&g_counts[d.y], 1);
    }
}

__global__ __launch_bounds__(SCAN_B) void bsum_k() {
    int i = blockIdx.x * SCAN_B + threadIdx.x;
    int c = (i < N_NODES) ? g_counts[i] : 0;
#pragma unroll
    for (int o = 16; o; o >>= 1) c += __shfl_xor_sync(0xffffffffu, c, o);
    __shared__ int ws[SCAN_B / 32];
    if ((threadIdx.x & 31) == 0) ws[threadIdx.x >> 5] = c;
    __syncthreads();
    if (threadIdx.x < SCAN_B / 32) {
        int v = ws[threadIdx.x];
#pragma unroll
        for (int o = SCAN_B / 64; o; o >>= 1) v += __shfl_xor_sync(0xffffffffu, v, o);
        if (threadIdx.x == 0) g_bsum[blockIdx.x] = v;
    }
}

__global__ __launch_bounds__(512) void scan_bsums_k() {
    __shared__ int s[512];
    int t = threadIdx.x;
    int v = (t < SCAN_NB) ? g_bsum[t] : 0;
    s[t] = v;
    __syncthreads();
    for (int d = 1; d < 512; d <<= 1) {
        int x = 0;
        if (t >= d) x = s[t - d];
        __syncthreads();
        s[t] += x;
        __syncthreads();
    }
    if (t < SCAN_NB) g_boff[t] = s[t] - v;
    if (t == 511) g_off[N_NODES] = s[SCAN_NB - 1];
}

__global__ __launch_bounds__(SCAN_B) void write_off_k() {
    int i = blockIdx.x * SCAN_B + threadIdx.x;
    int lane = threadIdx.x & 31;
    int wid = threadIdx.x >> 5;
    int c = (i < N_NODES) ? g_counts[i] : 0;
    int inc = c;
#pragma unroll
    for (int d = 1; d < 32; d <<= 1) {
        int x = __shfl_up_sync(0xffffffffu, inc, d);
        if (lane >= d) inc += x;
    }
    __shared__ int wsum[SCAN_B / 32];
    if (lane == 31) wsum[wid] = inc;
    __syncthreads();
    if (threadIdx.x == 0) {
        int run = 0;
#pragma unroll
        for (int wv = 0; wv < SCAN_B / 32; wv++) {
            int x = wsum[wv];
            wsum[wv] = run;
            run += x;
        }
    }
    __syncthreads();
    int off = g_boff[blockIdx.x] + wsum[wid] + inc - c;
    if (i < N_NODES) {
        g_off[i] = off;
        g_cursor[i] = off;
    }
}

__global__ void fill_k(const int* __restrict__ edge_index) {
    int t = blockIdx.x * blockDim.x + threadIdx.x;
    int e = t * 2;
    if (e < N_EDGES) {
        int2 s = *(const int2*)(edge_index + e);
        int2 d = *(const int2*)(edge_index + N_EDGES + e);
        int p0 = atomicAdd(&g_cursor[d.x], 1);
        g_csr_src[p0] = s.x;
        int p1 = atomicAdd(&g_cursor[d.y], 1);
        g_csr_src[p1] = s.y;
    }
}

// ---------------- tensor-core GEMM + fused attention-dot epilogue (h -> fp16) ----------------
#define SMEM_STRIDE 40

__device__ __forceinline__ void mma16816(float* d,
                                         uint32_t a0, uint32_t a1, uint32_t a2, uint32_t a3,
                                         uint32_t b0, uint32_t b1) {
    asm volatile(
        "mma.sync.aligned.m16n8k16.row.col.f32.bf16.bf16.f32 "
        "{%0,%1,%2,%3}, {%4,%5,%6,%7}, {%8,%9}, {%0,%1,%2,%3};\n"
        : "+f"(d[0]), "+f"(d[1]), "+f"(d[2]), "+f"(d[3])
        : "r"(a0), "r"(a1), "r"(a2), "r"(a3), "r"(b0), "r"(b1));
}

__global__ __launch_bounds__(256) void gemm_mma_k(const float* __restrict__ A,
                                                  const float* __restrict__ a1_src,
                                                  const float* __restrict__ a1_dst) {
    __shared__ __nv_bfloat16 As_hi[128][SMEM_STRIDE];
    __shared__ __nv_bfloat16 As_lo[128][SMEM_STRIDE];
    __shared__ __nv_bfloat16 Bs_hi[128][SMEM_STRIDE];
    __shared__ __nv_bfloat16 Bs_lo[128][SMEM_STRIDE];
    __shared__ float es_s[128][2], ed_s[128][2];

    const int tid = threadIdx.x;
    const int block_row = blockIdx.x * 128;
    const int w = tid >> 5, l = tid & 31;
    const int warp_m = (w >> 1) * 32;
    const int warp_n = (w & 1) * 64;
    const int nhalf = w & 1;

    float acc[2][8][4];
#pragma unroll
    for (int i = 0; i < 2; i++)
#pragma unroll
        for (int j = 0; j < 8; j++)
#pragma unroll
            for (int q = 0; q < 4; q++) acc[i][j][q] = 0.f;

    const int ar = tid >> 1;
    const int ac = (tid & 1) * 16;

    for (int k0 = 0; k0 < F_IN; k0 += 32) {
        {
            int gr = block_row + ar;
#pragma unroll
            for (int j = 0; j < 4; j++) {
                float4 v = make_float4(0.f, 0.f, 0.f, 0.f);
                if (gr < N_NODES)
                    v = *(const float4*)(A + (size_t)gr * F_IN + k0 + ac + j * 4);
                float xs[4] = {v.x, v.y, v.z, v.w};
                __nv_bfloat16 hi[4], lo[4];
#pragma unroll
                for (int c = 0; c < 4; c++) {
                    hi[c] = __float2bfloat16(xs[c]);
                    lo[c] = __float2bfloat16(xs[c] - __bfloat162float(hi[c]));
                }
                __nv_bfloat162* ph = (__nv_bfloat162*)&As_hi[ar][ac + j * 4];
                __nv_bfloat162* pl = (__nv_bfloat162*)&As_lo[ar][ac + j * 4];
                ph[0] = __nv_bfloat162(hi[0], hi[1]);
                ph[1] = __nv_bfloat162(hi[2], hi[3]);
                pl[0] = __nv_bfloat162(lo[0], lo[1]);
                pl[1] = __nv_bfloat162(lo[2], lo[3]);
            }
        }
        {
            const __nv_bfloat16* bh = g_Bt_hi + (size_t)ar * F_IN + k0 + ac;
            const __nv_bfloat16* bl = g_Bt_lo + (size_t)ar * F_IN + k0 + ac;
            *(uint4*)&Bs_hi[ar][ac] = *(const uint4*)bh;
            *(uint4*)&Bs_hi[ar][ac + 8] = *(const uint4*)(bh + 8);
            *(uint4*)&Bs_lo[ar][ac] = *(const uint4*)bl;
            *(uint4*)&Bs_lo[ar][ac + 8] = *(const uint4*)(bl + 8);
        }
        __syncthreads();

#pragma unroll
        for (int ks = 0; ks < 32; ks += 16) {
            const int fr = l >> 2;
            const int fc = ks + (l & 3) * 2;
            uint32_t ah[2][4], al[2][4];
#pragma unroll
            for (int mf = 0; mf < 2; mf++) {
                int r = warp_m + mf * 16 + fr;
                ah[mf][0] = *(const uint32_t*)&As_hi[r][fc];
                ah[mf][1] = *(const uint32_t*)&As_hi[r + 8][fc];
                ah[mf][2] = *(const uint32_t*)&As_hi[r][fc + 8];
                ah[mf][3] = *(const uint32_t*)&As_hi[r + 8][fc + 8];
                al[mf][0] = *(const uint32_t*)&As_lo[r][fc];
                al[mf][1] = *(const uint32_t*)&As_lo[r + 8][fc];
                al[mf][2] = *(const uint32_t*)&As_lo[r][fc + 8];
                al[mf][3] = *(const uint32_t*)&As_lo[r + 8][fc + 8];
            }
#pragma unroll
            for (int nf = 0; nf < 8; nf++) {
                int n = warp_n + nf * 8 + fr;
                uint32_t bh0 = *(const uint32_t*)&Bs_hi[n][fc];
                uint32_t bh1 = *(const uint32_t*)&Bs_hi[n][fc + 8];
                uint32_t bl0 = *(const uint32_t*)&Bs_lo[n][fc];
                uint32_t bl1 = *(const uint32_t*)&Bs_lo[n][fc + 8];
#pragma unroll
                for (int mf = 0; mf < 2; mf++) {
                    mma16816(acc[mf][nf], ah[mf][0], ah[mf][1], ah[mf][2], ah[mf][3], bh0, bh1);
                    mma16816(acc[mf][nf], ah[mf][0], ah[mf][1], ah[mf][2], ah[mf][3], bl0, bl1);
                    mma16816(acc[mf][nf], al[mf][0], al[mf][1], al[mf][2], al[mf][3], bh0, bh1);
                }
            }
        }
        __syncthreads();
    }

    const int fr = l >> 2;
    const int quad = l & 3;

#pragma unroll
    for (int mf = 0; mf < 2; mf++) {
        int rl0 = warp_m + mf * 16 + fr;
        int rl1 = rl0 + 8;
        int r0 = block_row + rl0;
        int r1 = block_row + rl1;
        float es0 = 0.f, ed0 = 0.f, es1 = 0.f, ed1 = 0.f;
#pragma unroll
        for (int nf = 0; nf < 8; nf++) {
            int cc = warp_n + nf * 8 + quad * 2;
            float as0 = a1_src[cc], as1 = a1_src[cc + 1];
            float ad0 = a1_dst[cc], ad1 = a1_dst[cc + 1];
            es0 += acc[mf][nf][0] * as0 + acc[mf][nf][1] * as1;
            ed0 += acc[mf][nf][0] * ad0 + acc[mf][nf][1] * ad1;
            es1 += acc[mf][nf][2] * as0 + acc[mf][nf][3] * as1;
            ed1 += acc[mf][nf][2] * ad0 + acc[mf][nf][3] * ad1;
            if (r0 < N_NODES) {
                __half2 hv = __floats2half2_rn(acc[mf][nf][0], acc[mf][nf][1]);
                g_h16[(size_t)r0 * (F_HID / 2) + (cc >> 1)] = *(uint32_t*)&hv;
            }
            if (r1 < N_NODES) {
                __half2 hv = __floats2half2_rn(acc[mf][nf][2], acc[mf][nf][3]);
                g_h16[(size_t)r1 * (F_HID / 2) + (cc >> 1)] = *(uint32_t*)&hv;
            }
        }
#pragma unroll
        for (int o = 1; o <= 2; o <<= 1) {
            es0 += __shfl_xor_sync(0xffffffffu, es0, o);
            ed0 += __shfl_xor_sync(0xffffffffu, ed0, o);
            es1 += __shfl_xor_sync(0xffffffffu, es1, o);
            ed1 += __shfl_xor_sync(0xffffffffu, ed1, o);
        }
        if (quad == 0) {
            es_s[rl0][nhalf] = es0;
            ed_s[rl0][nhalf] = ed0;
            es_s[rl1][nhalf] = es1;
            ed_s[rl1][nhalf] = ed1;
        }
    }
    __syncthreads();
    if (tid < 128) {
        int gr = block_row + tid;
        if (gr < N_NODES) {
            g_es1[gr] = es_s[tid][0] + es_s[tid][1];
            g_ed1[gr] = ed_s[tid][0] + ed_s[tid][1];
        }
    }
}

__device__ __forceinline__ float leaky(float x) { return x > 0.f ? x : 0.2f * x; }

// ---------------- layer-1 aggregation: TWO nodes per warp, inline weights ----------------
__global__ __launch_bounds__(256) void agg1_k(const float* __restrict__ Wmu,
                                              const float* __restrict__ amus,
                                              const float* __restrict__ amud) {
    int warp = (blockIdx.x * blockDim.x + threadIdx.x) >> 5;
    int lane = threadIdx.x & 31;
    if (warp >= N_NODES / 2) return;
    int v0 = warp * 2, v1 = v0 + 1;
    int b0 = g_off[v0], e0 = g_off[v0 + 1];
    int e1 = g_off[v1 + 1];
    int b1 = e0;
    float edv0 = g_ed1[v0];
    float edv1 = g_ed1[v1];

    float A00 = 0.f, A01 = 0.f, A02 = 0.f, A03 = 0.f, D0 = 0.f;
    float A10 = 0.f, A11 = 0.f, A12 = 0.f, A13 = 0.f, D1 = 0.f;

    int j0 = b0, j1 = b1;
    while (j0 + 2 <= e0 && j1 + 2 <= e1) {
        int s00 = g_csr_src[j0], s01 = g_csr_src[j0 + 1];
        int s10 = g_csr_src[j1], s11 = g_csr_src[j1 + 1];
        float w00 = expf(leaky(g_es1[s00] + edv0));
        float w01 = expf(leaky(g_es1[s01] + edv0));
        float w10 = expf(leaky(g_es1[s10] + edv1));
        float w11 = expf(leaky(g_es1[s11] + edv1));
        const uint32_t* p00 = g_h16 + (size_t)s00 * (F_HID / 2);
        const uint32_t* p01 = g_h16 + (size_t)s01 * (F_HID / 2);
        const uint32_t* p10 = g_h16 + (size_t)s10 * (F_HID / 2);
        const uint32_t* p11 = g_h16 + (size_t)s11 * (F_HID / 2);
        uint32_t q00a = p00[lane], q00b = p00[lane + 32];
        uint32_t q01a = p01[lane], q01b = p01[lane + 32];
        uint32_t q10a = p10[lane], q10b = p10[lane + 32];
        uint32_t q11a = p11[lane], q11b = p11[lane + 32];
        float2 x00a = __half22float2(*(__half2*)&q00a), x00b = __half22float2(*(__half2*)&q00b);
        float2 x01a = __half22float2(*(__half2*)&q01a), x01b = __half22float2(*(__half2*)&q01b);
        float2 x10a = __half22float2(*(__half2*)&q10a), x10b = __half22float2(*(__half2*)&q10b);
        float2 x11a = __half22float2(*(__half2*)&q11a), x11b = __half22float2(*(__half2*)&q11b);
        D0 += w00 + w01;
        A00 += w00 * x00a.x + w01 * x01a.x;
        A01 += w00 * x00a.y + w01 * x01a.y;
        A02 += w00 * x00b.x + w01 * x01b.x;
        A03 += w00 * x00b.y + w01 * x01b.y;
        D1 += w10 + w11;
        A10 += w10 * x10a.x + w11 * x11a.x;
        A11 += w10 * x10a.y + w11 * x11a.y;
        A12 += w10 * x10b.x + w11 * x11b.x;
        A13 += w10 * x10b.y + w11 * x11b.y;
        j0 += 2;
        j1 += 2;
    }
    for (; j0 < e0; j0++) {
        int s = g_csr_src[j0];
        float wg = expf(leaky(g_es1[s] + edv0));
        const uint32_t* p = g_h16 + (size_t)s * (F_HID / 2);
        uint32_t qa = p[lane], qb = p[lane + 32];
        float2 xa = __half22float2(*(__half2*)&qa), xb = __half22float2(*(__half2*)&qb);
        D0 += wg;
        A00 += wg * xa.x;
        A01 += wg * xa.y;
        A02 += wg * xb.x;
        A03 += wg * xb.y;
    }
    for (; j1 < e1; j1++) {
        int s = g_csr_src[j1];
        float wg = expf(leaky(g_es1[s] + edv1));
        const uint32_t* p = g_h16 + (size_t)s * (F_HID / 2);
        uint32_t qa = p[lane], qb = p[lane + 32];
        float2 xa = __half22float2(*(__half2*)&qa), xb = __half22float2(*(__half2*)&qb);
        D1 += wg;
        A10 += wg * xa.x;
        A11 += wg * xa.y;
        A12 += wg * xb.x;
        A13 += wg * xb.y;
    }

    int f0 = 2 * lane, f1 = 2 * lane + 1, f2 = 64 + 2 * lane, f3 = 64 + 2 * lane + 1;
    float Wm00 = Wmu[f0 * 2], Wm01 = Wmu[f0 * 2 + 1];
    float Wm10 = Wmu[f1 * 2], Wm11 = Wmu[f1 * 2 + 1];
    float Wm20 = Wmu[f2 * 2], Wm21 = Wmu[f2 * 2 + 1];
    float Wm30 = Wmu[f3 * 2], Wm31 = Wmu[f3 * 2 + 1];

    float h00 = 0.f, h01 = 0.f, h10 = 0.f, h11 = 0.f;
    if (b0 < e0) {
        float inv = 1.f / fmaxf(D0, 1e-16f);
        float a0 = fmaxf(A00 * inv, 0.f), a1 = fmaxf(A01 * inv, 0.f);
        float a2 = fmaxf(A02 * inv, 0.f), a3 = fmaxf(A03 * inv, 0.f);
        h00 = a0 * Wm00 + a1 * Wm10 + a2 * Wm20 + a3 * Wm30;
        h01 = a0 * Wm01 + a1 * Wm11 + a2 * Wm21 + a3 * Wm31;
    }
    if (b1 < e1) {
        float inv = 1.f / fmaxf(D1, 1e-16f);
        float a0 = fmaxf(A10 * inv, 0.f), a1 = fmaxf(A11 * inv, 0.f);
        float a2 = fmaxf(A12 * inv, 0.f), a3 = fmaxf(A13 * inv, 0.f);
        h10 = a0 * Wm00 + a1 * Wm10 + a2 * Wm20 + a3 * Wm30;
        h11 = a0 * Wm01 + a1 * Wm11 + a2 * Wm21 + a3 * Wm31;
    }
#pragma unroll
    for (int o = 16; o; o >>= 1) {
        h00 += __shfl_xor_sync(0xffffffffu, h00, o);
        h01 += __shfl_xor_sync(0xffffffffu, h01, o);
        h10 += __shfl_xor_sync(0xffffffffu, h10, o);
        h11 += __shfl_xor_sync(0xffffffffu, h11, o);
    }
    if (lane == 0) {
        float as0 = amus[0], as1 = amus[1], ad0 = amud[0], ad1 = amud[1];
        g_h2e[v0] = make_float4(h00, h01, h00 * as0 + h01 * as1, h00 * ad0 + h01 * ad1);
        g_h2e[v1] = make_float4(h10, h11, h10 * as0 + h11 * as1, h10 * ad0 + h11 * ad1);
    }
}

// ---------------- layer-2 agg + logits: half-warp per node (avg degree 16) ----------------
__global__ __launch_bounds__(256) void agg2_logits_k(const int* __restrict__ input_y,
                                                     const float* __restrict__ ssw,
                                                     const float* __restrict__ ssb,
                                                     float* __restrict__ out,
                                                     float* __restrict__ mu_out) {
    __shared__ float sw0[N_SAMP], sw1[N_SAMP], sb[N_SAMP];
    for (int i = threadIdx.x; i < N_SAMP / 4; i += blockDim.x) {
        *(float4*)&sw0[i * 4] = *(const float4*)&g_sw0[i * 4];
        *(float4*)&sw1[i * 4] = *(const float4*)&g_sw1[i * 4];
        *(float4*)&sb[i * 4]  = *(const float4*)&g_sb[i * 4];
    }
    __syncthreads();

    int warp = (blockIdx.x * blockDim.x + threadIdx.x) >> 5;
    int lane = threadIdx.x & 31;
    if (warp >= N_NODES / 2) return;
    int v0 = warp * 2, v1 = v0 + 1;
    int b0 = g_off[v0], e0 = g_off[v0 + 1];
    int e1 = g_off[v1 + 1];
    int b1 = e0;

    // half-warp split: lanes 0-15 -> v0, lanes 16-31 -> v1
    int half = lane >> 4;
    int hl = lane & 15;
    int jb = (half ? b1 : b0) + hl;
    int je = half ? e1 : e0;
    float edv = g_h2e[half ? v1 : v0].w;

    float d = 0.f, a0 = 0.f, a1 = 0.f;
    for (int j = jb; j < je; j += 16) {
        int s = g_csr_src[j];
        float4 he = g_h2e[s];
        float w = expf(leaky(he.z + edv));
        d += w; a0 += w * he.x; a1 += w * he.y;
    }
#pragma unroll
    for (int o = 8; o; o >>= 1) {
        d  += __shfl_xor_sync(0xffffffffu, d, o);
        a0 += __shfl_xor_sync(0xffffffffu, a0, o);
        a1 += __shfl_xor_sync(0xffffffffu, a1, o);
    }
    float inv = 1.f / fmaxf(d, 1e-16f);
    float mx = a0 * inv;   // this half's node mu0
    float my = a1 * inv;   // this half's node mu1
    // broadcast both nodes' mu to all lanes
    float mu00 = __shfl_sync(0xffffffffu, mx, 0);
    float mu01 = __shfl_sync(0xffffffffu, my, 0);
    float mu10 = __shfl_sync(0xffffffffu, mx, 16);
    float mu11 = __shfl_sync(0xffffffffu, my, 16);

    float* row0 = out + (size_t)v0 * (N_SAMP + 1);
    float* row1 = out + (size_t)v1 * (N_SAMP + 1);
    if (lane == 0) {
        mu_out[2 * v0] = mu00; mu_out[2 * v0 + 1] = mu01;
        mu_out[2 * v1] = mu10; mu_out[2 * v1 + 1] = mu11;
        int y0 = input_y[v0];
        int y1 = input_y[v1];
        __stcs(&row0[0], mu00 * ssw[2 * y0] + mu01 * ssw[2 * y0 + 1] + ssb[y0]);
        __stcs(&row1[0], mu10 * ssw[2 * y1] + mu11 * ssw[2 * y1 + 1] + ssb[y1]);
    }
    for (int c = lane + 1; c <= N_SAMP; c += 32) {
        int s = c - 1;
        float b = sb[s], s0v = sw0[s], s1v = sw1[s];
        __stcs(&row0[c], mu00 * s0v + mu01 * s1v + b);
        __stcs(&row1[c], mu10 * s0v + mu11 * s1v + b);
    }
}

// ---------------- launch (fork/join: CSR chain overlaps prep+GEMM) ----------------
static cudaStream_t g_s2 = nullptr;
static cudaEvent_t g_ev_fork = nullptr;
static cudaEvent_t g_ev_join = nullptr;

extern "C" void kernel_launch(void* const* d_in, const int* in_sizes, int n_in,
                              void* d_out, int out_size) {
    const float* X         = (const float*)d_in[0];
    const int*   input_y   = (const int*)d_in[2];
    const int*   edge_idx  = (const int*)d_in[3];
    const int*   sample_ids= (const int*)d_in[4];
    const float* W1        = (const float*)d_in[5];
    const float* a1_src    = (const float*)d_in[6];
    const float* a1_dst    = (const float*)d_in[7];
    const float* W_mu      = (const float*)d_in[8];
    const float* amu_src   = (const float*)d_in[9];
    const float* amu_dst   = (const float*)d_in[10];
    const float* ss_weight = (const float*)d_in[14];
    const float* ss_bias   = (const float*)d_in[15];
    float* out = (float*)d_out;

    float* mu_out = out + (size_t)N_NODES * (N_SAMP + 1);

    if (g_s2 == nullptr) {
        cudaStreamCreateWithFlags(&g_s2, cudaStreamNonBlocking);
        cudaEventCreateWithFlags(&g_ev_fork, cudaEventDisableTiming);
        cudaEventCreateWithFlags(&g_ev_join, cudaEventDisableTiming);
    }

    // fork immediately: CSR chain on s2, prep+GEMM on main
    cudaEventRecord(g_ev_fork, 0);
    cudaStreamWaitEvent(g_s2, g_ev_fork, 0);
    zero_counts_k<<<(N_NODES + 255) / 256, 256, 0, g_s2>>>();
    hist_k<<<(N_EDGES / 2 + 255) / 256, 256, 0, g_s2>>>(edge_idx);
    bsum_k<<<SCAN_NB, SCAN_B, 0, g_s2>>>();
    scan_bsums_k<<<1, 512, 0, g_s2>>>();
    write_off_k<<<SCAN_NB, SCAN_B, 0, g_s2>>>();
    fill_k<<<(N_EDGES / 2 + 255) / 256, 256, 0, g_s2>>>(edge_idx);
    cudaEventRecord(g_ev_join, g_s2);

    // main stream: W split + sample gather, then tensor-core GEMM (concurrent with s2)
    prep_k<<<(F_HID * F_IN + 255) / 256, 256>>>(W1, sample_ids, ss_weight, ss_bias);
    gemm_mma_k<<<(N_NODES + 127) / 128, 256>>>(X, a1_src, a1_dst);

    // join, then two-node-per-warp aggregation phases (weights inline)
    cudaStreamWaitEvent(0, g_ev_join, 0);
    int pair_blocks = ((N_NODES / 2) * 32 + 255) / 256;   // 6250
    agg1_k<<<pair_blocks, 256>>>(W_mu, amu_src, amu_dst);
    agg2_logits_k<<<pair_blocks, 256>>>(input_y, ss_weight, ss_bias, out, mu_out);
}

// round 13
// speedup vs baseline: 1.0018x; 1.0018x over previous
#include <cuda_runtime.h>
#include <cuda_bf16.h>
#include <cuda_fp16.h>
#include <math.h>
#include <stdint.h>

#define N_NODES 100000
#define N_EDGES 1600000
#define F_IN 256
#define F_HID 128
#define VOCAB 100000
#define N_SAMP 512

#define SCAN_B 256
#define SCAN_NB ((N_NODES + SCAN_B - 1) / SCAN_B)   // 391

// ---------------- scratch (static __device__ — no allocations) ----------------
__device__ uint32_t g_h16[(size_t)N_NODES * (F_HID / 2)];   // h as half2 pairs, 25.6 MB
__device__ float g_es1[N_NODES];
__device__ float g_ed1[N_NODES];
__device__ int   g_counts[N_NODES];
__device__ int   g_off[N_NODES + 1];
__device__ int   g_cursor[N_NODES];
__device__ int   g_csr_src[N_EDGES];
__device__ float4 g_h2e[N_NODES];           // {h2_0, h2_1, es2, ed2}
__device__ int   g_bsum[SCAN_NB];
__device__ int   g_boff[SCAN_NB];
__device__ __nv_bfloat16 g_Bt_hi[F_HID * F_IN];
__device__ __nv_bfloat16 g_Bt_lo[F_HID * F_IN];
__device__ float g_sw0[N_SAMP];
__device__ float g_sw1[N_SAMP];
__device__ float g_sb[N_SAMP];

// ---------------- s2 branch: zero counts ----------------
__global__ void zero_counts_k() {
    int i = blockIdx.x * blockDim.x + threadIdx.x;
    if (i < N_NODES) g_counts[i] = 0;
}

// ---------------- main branch: W1 split + sample-table gather ----------------
__global__ void prep_k(const float* __restrict__ W1,
                       const int* __restrict__ sample_ids,
                       const float* __restrict__ ssw,
                       const float* __restrict__ ssb) {
    int i = blockIdx.x * blockDim.x + threadIdx.x;
    if (i < F_HID * F_IN) {
        int n = i / F_IN;
        int k = i % F_IN;
        float w = W1[(size_t)k * F_HID + n];
        __nv_bfloat16 hi = __float2bfloat16(w);
        float r = w - __bfloat162float(hi);
        g_Bt_hi[i] = hi;
        g_Bt_lo[i] = __float2bfloat16(r);
    }
    if (i < N_SAMP) {
        int sid = sample_ids[i];
        g_sw0[i] = ssw[2 * sid];
        g_sw1[i] = ssw[2 * sid + 1];
        g_sb[i] = ssb[sid];
    }
}

// ---------------- CSR build (vectorized 2 edges/thread) ----------------
__global__ void hist_k(const int* __restrict__ edge_index) {
    int t = blockIdx.x * blockDim.x + threadIdx.x;
    int e = t * 2;
    if (e < N_EDGES) {
        int2 d = *(const int2*)(edge_index + N_EDGES + e);
        atomicAdd(&g_counts[d.x], 1);
        atomicAdd(&g_counts[d.y], 1);
    }
}

__global__ __launch_bounds__(SCAN_B) void bsum_k() {
    int i = blockIdx.x * SCAN_B + threadIdx.x;
    int c = (i < N_NODES) ? g_counts[i] : 0;
#pragma unroll
    for (int o = 16; o; o >>= 1) c += __shfl_xor_sync(0xffffffffu, c, o);
    __shared__ int ws[SCAN_B / 32];
    if ((threadIdx.x & 31) == 0) ws[threadIdx.x >> 5] = c;
    __syncthreads();
    if (threadIdx.x < SCAN_B / 32) {
        int v = ws[threadIdx.x];
#pragma unroll
        for (int o = SCAN_B / 64; o; o >>= 1) v += __shfl_xor_sync(0xffffffffu, v, o);
        if (threadIdx.x == 0) g_bsum[blockIdx.x] = v;
    }
}

__global__ __launch_bounds__(512) void scan_bsums_k() {
    __shared__ int s[512];
    int t = threadIdx.x;
    int v = (t < SCAN_NB) ? g_bsum[t] : 0;
    s[t] = v;
    __syncthreads();
    for (int d = 1; d < 512; d <<= 1) {
        int x = 0;
        if (t >= d) x = s[t - d];
        __syncthreads();
        s[t] += x;
        __syncthreads();
    }
    if (t < SCAN_NB) g_boff[t] = s[t] - v;
    if (t == 511) g_off[N_NODES] = s[SCAN_NB - 1];
}

__global__ __launch_bounds__(SCAN_B) void write_off_k() {
    int i = blockIdx.x * SCAN_B + threadIdx.x;
    int lane = threadIdx.x & 31;
    int wid = threadIdx.x >> 5;
    int c = (i < N_NODES) ? g_counts[i] : 0;
    int inc = c;
#pragma unroll
    for (int d = 1; d < 32; d <<= 1) {
        int x = __shfl_up_sync(0xffffffffu, inc, d);
        if (lane >= d) inc += x;
    }
    __shared__ int wsum[SCAN_B / 32];
    if (lane == 31) wsum[wid] = inc;
    __syncthreads();
    if (threadIdx.x == 0) {
        int run = 0;
#pragma unroll
        for (int wv = 0; wv < SCAN_B / 32; wv++) {
            int x = wsum[wv];
            wsum[wv] = run;
            run += x;
        }
    }
    __syncthreads();
    int off = g_boff[blockIdx.x] + wsum[wid] + inc - c;
    if (i < N_NODES) {
        g_off[i] = off;
        g_cursor[i] = off;
    }
}

__global__ void fill_k(const int* __restrict__ edge_index) {
    int t = blockIdx.x * blockDim.x + threadIdx.x;
    int e = t * 2;
    if (e < N_EDGES) {
        int2 s = *(const int2*)(edge_index + e);
        int2 d = *(const int2*)(edge_index + N_EDGES + e);
        int p0 = atomicAdd(&g_cursor[d.x], 1);
        g_csr_src[p0] = s.x;
        int p1 = atomicAdd(&g_cursor[d.y], 1);
        g_csr_src[p1] = s.y;
    }
}

// ---------------- tensor-core GEMM + fused attention-dot epilogue (h -> fp16) ----------------
#define SMEM_STRIDE 40

__device__ __forceinline__ void mma16816(float* d,
                                         uint32_t a0, uint32_t a1, uint32_t a2, uint32_t a3,
                                         uint32_t b0, uint32_t b1) {
    asm volatile(
        "mma.sync.aligned.m16n8k16.row.col.f32.bf16.bf16.f32 "
        "{%0,%1,%2,%3}, {%4,%5,%6,%7}, {%8,%9}, {%0,%1,%2,%3};\n"
        : "+f"(d[0]), "+f"(d[1]), "+f"(d[2]), "+f"(d[3])
        : "r"(a0), "r"(a1), "r"(a2), "r"(a3), "r"(b0), "r"(b1));
}

__global__ __launch_bounds__(256) void gemm_mma_k(const float* __restrict__ A,
                                                  const float* __restrict__ a1_src,
                                                  const float* __restrict__ a1_dst) {
    __shared__ __nv_bfloat16 As_hi[128][SMEM_STRIDE];
    __shared__ __nv_bfloat16 As_lo[128][SMEM_STRIDE];
    __shared__ __nv_bfloat16 Bs_hi[128][SMEM_STRIDE];
    __shared__ __nv_bfloat16 Bs_lo[128][SMEM_STRIDE];
    __shared__ float es_s[128][2], ed_s[128][2];

    const int tid = threadIdx.x;
    const int block_row = blockIdx.x * 128;
    const int w = tid >> 5, l = tid & 31;
    const int warp_m = (w >> 1) * 32;
    const int warp_n = (w & 1) * 64;
    const int nhalf = w & 1;

    float acc[2][8][4];
#pragma unroll
    for (int i = 0; i < 2; i++)
#pragma unroll
        for (int j = 0; j < 8; j++)
#pragma unroll
            for (int q = 0; q < 4; q++) acc[i][j][q] = 0.f;

    const int ar = tid >> 1;
    const int ac = (tid & 1) * 16;

    for (int k0 = 0; k0 < F_IN; k0 += 32) {
        {
            int gr = block_row + ar;
#pragma unroll
            for (int j = 0; j < 4; j++) {
                float4 v = make_float4(0.f, 0.f, 0.f, 0.f);
                if (gr < N_NODES)
                    v = *(const float4*)(A + (size_t)gr * F_IN + k0 + ac + j * 4);
                float xs[4] = {v.x, v.y, v.z, v.w};
                __nv_bfloat16 hi[4], lo[4];
#pragma unroll
                for (int c = 0; c < 4; c++) {
                    hi[c] = __float2bfloat16(xs[c]);
                    lo[c] = __float2bfloat16(xs[c] - __bfloat162float(hi[c]));
                }
                __nv_bfloat162* ph = (__nv_bfloat162*)&As_hi[ar][ac + j * 4];
                __nv_bfloat162* pl = (__nv_bfloat162*)&As_lo[ar][ac + j * 4];
                ph[0] = __nv_bfloat162(hi[0], hi[1]);
                ph[1] = __nv_bfloat162(hi[2], hi[3]);
                pl[0] = __nv_bfloat162(lo[0], lo[1]);
                pl[1] = __nv_bfloat162(lo[2], lo[3]);
            }
        }
        {
            const __nv_bfloat16* bh = g_Bt_hi + (size_t)ar * F_IN + k0 + ac;
            const __nv_bfloat16* bl = g_Bt_lo + (size_t)ar * F_IN + k0 + ac;
            *(uint4*)&Bs_hi[ar][ac] = *(const uint4*)bh;
            *(uint4*)&Bs_hi[ar][ac + 8] = *(const uint4*)(bh + 8);
            *(uint4*)&Bs_lo[ar][ac] = *(const uint4*)bl;
            *(uint4*)&Bs_lo[ar][ac + 8] = *(const uint4*)(bl + 8);
        }
        __syncthreads();

#pragma unroll
        for (int ks = 0; ks < 32; ks += 16) {
            const int fr = l >> 2;
            const int fc = ks + (l & 3) * 2;
            uint32_t ah[2][4], al[2][4];
#pragma unroll
            for (int mf = 0; mf < 2; mf++) {
                int r = warp_m + mf * 16 + fr;
                ah[mf][0] = *(const uint32_t*)&As_hi[r][fc];
                ah[mf][1] = *(const uint32_t*)&As_hi[r + 8][fc];
                ah[mf][2] = *(const uint32_t*)&As_hi[r][fc + 8];
                ah[mf][3] = *(const uint32_t*)&As_hi[r + 8][fc + 8];
                al[mf][0] = *(const uint32_t*)&As_lo[r][fc];
                al[mf][1] = *(const uint32_t*)&As_lo[r + 8][fc];
                al[mf][2] = *(const uint32_t*)&As_lo[r][fc + 8];
                al[mf][3] = *(const uint32_t*)&As_lo[r + 8][fc + 8];
            }
#pragma unroll
            for (int nf = 0; nf < 8; nf++) {
                int n = warp_n + nf * 8 + fr;
                uint32_t bh0 = *(const uint32_t*)&Bs_hi[n][fc];
                uint32_t bh1 = *(const uint32_t*)&Bs_hi[n][fc + 8];
                uint32_t bl0 = *(const uint32_t*)&Bs_lo[n][fc];
                uint32_t bl1 = *(const uint32_t*)&Bs_lo[n][fc + 8];
#pragma unroll
                for (int mf = 0; mf < 2; mf++) {
                    mma16816(acc[mf][nf], ah[mf][0], ah[mf][1], ah[mf][2], ah[mf][3], bh0, bh1);
                    mma16816(acc[mf][nf], ah[mf][0], ah[mf][1], ah[mf][2], ah[mf][3], bl0, bl1);
                    mma16816(acc[mf][nf], al[mf][0], al[mf][1], al[mf][2], al[mf][3], bh0, bh1);
                }
            }
        }
        __syncthreads();
    }

    const int fr = l >> 2;
    const int quad = l & 3;

#pragma unroll
    for (int mf = 0; mf < 2; mf++) {
        int rl0 = warp_m + mf * 16 + fr;
        int rl1 = rl0 + 8;
        int r0 = block_row + rl0;
        int r1 = block_row + rl1;
        float es0 = 0.f, ed0 = 0.f, es1 = 0.f, ed1 = 0.f;
#pragma unroll
        for (int nf = 0; nf < 8; nf++) {
            int cc = warp_n + nf * 8 + quad * 2;
            float as0 = a1_src[cc], as1 = a1_src[cc + 1];
            float ad0 = a1_dst[cc], ad1 = a1_dst[cc + 1];
            es0 += acc[mf][nf][0] * as0 + acc[mf][nf][1] * as1;
            ed0 += acc[mf][nf][0] * ad0 + acc[mf][nf][1] * ad1;
            es1 += acc[mf][nf][2] * as0 + acc[mf][nf][3] * as1;
            ed1 += acc[mf][nf][2] * ad0 + acc[mf][nf][3] * ad1;
            if (r0 < N_NODES) {
                __half2 hv = __floats2half2_rn(acc[mf][nf][0], acc[mf][nf][1]);
                g_h16[(size_t)r0 * (F_HID / 2) + (cc >> 1)] = *(uint32_t*)&hv;
            }
            if (r1 < N_NODES) {
                __half2 hv = __floats2half2_rn(acc[mf][nf][2], acc[mf][nf][3]);
                g_h16[(size_t)r1 * (F_HID / 2) + (cc >> 1)] = *(uint32_t*)&hv;
            }
        }
#pragma unroll
        for (int o = 1; o <= 2; o <<= 1) {
            es0 += __shfl_xor_sync(0xffffffffu, es0, o);
            ed0 += __shfl_xor_sync(0xffffffffu, ed0, o);
            es1 += __shfl_xor_sync(0xffffffffu, es1, o);
            ed1 += __shfl_xor_sync(0xffffffffu, ed1, o);
        }
        if (quad == 0) {
            es_s[rl0][nhalf] = es0;
            ed_s[rl0][nhalf] = ed0;
            es_s[rl1][nhalf] = es1;
            ed_s[rl1][nhalf] = ed1;
        }
    }
    __syncthreads();
    if (tid < 128) {
        int gr = block_row + tid;
        if (gr < N_NODES) {
            g_es1[gr] = es_s[tid][0] + es_s[tid][1];
            g_ed1[gr] = ed_s[tid][0] + ed_s[tid][1];
        }
    }
}

__device__ __forceinline__ float leaky(float x) { return x > 0.f ? x : 0.2f * x; }

// ---------------- layer-1 aggregation: TWO nodes per warp, inline weights ----------------
__global__ __launch_bounds__(256) void agg1_k(const float* __restrict__ Wmu,
                                              const float* __restrict__ amus,
                                              const float* __restrict__ amud) {
    int warp = (blockIdx.x * blockDim.x + threadIdx.x) >> 5;
    int lane = threadIdx.x & 31;
    if (warp >= N_NODES / 2) return;
    int v0 = warp * 2, v1 = v0 + 1;
    int b0 = g_off[v0], e0 = g_off[v0 + 1];
    int e1 = g_off[v1 + 1];
    int b1 = e0;
    float edv0 = g_ed1[v0];
    float edv1 = g_ed1[v1];

    float A00 = 0.f, A01 = 0.f, A02 = 0.f, A03 = 0.f, D0 = 0.f;
    float A10 = 0.f, A11 = 0.f, A12 = 0.f, A13 = 0.f, D1 = 0.f;

    int j0 = b0, j1 = b1;
    while (j0 + 2 <= e0 && j1 + 2 <= e1) {
        int s00 = g_csr_src[j0], s01 = g_csr_src[j0 + 1];
        int s10 = g_csr_src[j1], s11 = g_csr_src[j1 + 1];
        float w00 = expf(leaky(g_es1[s00] + edv0));
        float w01 = expf(leaky(g_es1[s01] + edv0));
        float w10 = expf(leaky(g_es1[s10] + edv1));
        float w11 = expf(leaky(g_es1[s11] + edv1));
        const uint32_t* p00 = g_h16 + (size_t)s00 * (F_HID / 2);
        const uint32_t* p01 = g_h16 + (size_t)s01 * (F_HID / 2);
        const uint32_t* p10 = g_h16 + (size_t)s10 * (F_HID / 2);
        const uint32_t* p11 = g_h16 + (size_t)s11 * (F_HID / 2);
        uint32_t q00a = p00[lane], q00b = p00[lane + 32];
        uint32_t q01a = p01[lane], q01b = p01[lane + 32];
        uint32_t q10a = p10[lane], q10b = p10[lane + 32];
        uint32_t q11a = p11[lane], q11b = p11[lane + 32];
        float2 x00a = __half22float2(*(__half2*)&q00a), x00b = __half22float2(*(__half2*)&q00b);
        float2 x01a = __half22float2(*(__half2*)&q01a), x01b = __half22float2(*(__half2*)&q01b);
        float2 x10a = __half22float2(*(__half2*)&q10a), x10b = __half22float2(*(__half2*)&q10b);
        float2 x11a = __half22float2(*(__half2*)&q11a), x11b = __half22float2(*(__half2*)&q11b);
        D0 += w00 + w01;
        A00 += w00 * x00a.x + w01 * x01a.x;
        A01 += w00 * x00a.y + w01 * x01a.y;
        A02 += w00 * x00b.x + w01 * x01b.x;
        A03 += w00 * x00b.y + w01 * x01b.y;
        D1 += w10 + w11;
        A10 += w10 * x10a.x + w11 * x11a.x;
        A11 += w10 * x10a.y + w11 * x11a.y;
        A12 += w10 * x10b.x + w11 * x11b.x;
        A13 += w10 * x10b.y + w11 * x11b.y;
        j0 += 2;
        j1 += 2;
    }
    for (; j0 < e0; j0++) {
        int s = g_csr_src[j0];
        float wg = expf(leaky(g_es1[s] + edv0));
        const uint32_t* p = g_h16 + (size_t)s * (F_HID / 2);
        uint32_t qa = p[lane], qb = p[lane + 32];
        float2 xa = __half22float2(*(__half2*)&qa), xb = __half22float2(*(__half2*)&qb);
        D0 += wg;
        A00 += wg * xa.x;
        A01 += wg * xa.y;
        A02 += wg * xb.x;
        A03 += wg * xb.y;
    }
    for (; j1 < e1; j1++) {
        int s = g_csr_src[j1];
        float wg = expf(leaky(g_es1[s] + edv1));
        const uint32_t* p = g_h16 + (size_t)s * (F_HID / 2);
        uint32_t qa = p[lane], qb = p[lane + 32];
        float2 xa = __half22float2(*(__half2*)&qa), xb = __half22float2(*(__half2*)&qb);
        D1 += wg;
        A10 += wg * xa.x;
        A11 += wg * xa.y;
        A12 += wg * xb.x;
        A13 += wg * xb.y;
    }

    int f0 = 2 * lane, f1 = 2 * lane + 1, f2 = 64 + 2 * lane, f3 = 64 + 2 * lane + 1;
    float Wm00 = Wmu[f0 * 2], Wm01 = Wmu[f0 * 2 + 1];
    float Wm10 = Wmu[f1 * 2], Wm11 = Wmu[f1 * 2 + 1];
    float Wm20 = Wmu[f2 * 2], Wm21 = Wmu[f2 * 2 + 1];
    float Wm30 = Wmu[f3 * 2], Wm31 = Wmu[f3 * 2 + 1];

    float h00 = 0.f, h01 = 0.f, h10 = 0.f, h11 = 0.f;
    if (b0 < e0) {
        float inv = 1.f / fmaxf(D0, 1e-16f);
        float a0 = fmaxf(A00 * inv, 0.f), a1 = fmaxf(A01 * inv, 0.f);
        float a2 = fmaxf(A02 * inv, 0.f), a3 = fmaxf(A03 * inv, 0.f);
        h00 = a0 * Wm00 + a1 * Wm10 + a2 * Wm20 + a3 * Wm30;
        h01 = a0 * Wm01 + a1 * Wm11 + a2 * Wm21 + a3 * Wm31;
    }
    if (b1 < e1) {
        float inv = 1.f / fmaxf(D1, 1e-16f);
        float a0 = fmaxf(A10 * inv, 0.f), a1 = fmaxf(A11 * inv, 0.f);
        float a2 = fmaxf(A12 * inv, 0.f), a3 = fmaxf(A13 * inv, 0.f);
        h10 = a0 * Wm00 + a1 * Wm10 + a2 * Wm20 + a3 * Wm30;
        h11 = a0 * Wm01 + a1 * Wm11 + a2 * Wm21 + a3 * Wm31;
    }
#pragma unroll
    for (int o = 16; o; o >>= 1) {
        h00 += __shfl_xor_sync(0xffffffffu, h00, o);
        h01 += __shfl_xor_sync(0xffffffffu, h01, o);
        h10 += __shfl_xor_sync(0xffffffffu, h10, o);
        h11 += __shfl_xor_sync(0xffffffffu, h11, o);
    }
    if (lane == 0) {
        float as0 = amus[0], as1 = amus[1], ad0 = amud[0], ad1 = amud[1];
        g_h2e[v0] = make_float4(h00, h01, h00 * as0 + h01 * as1, h00 * ad0 + h01 * ad1);
        g_h2e[v1] = make_float4(h10, h11, h10 * as0 + h11 * as1, h10 * ad0 + h11 * ad1);
    }
}

// ---------------- layer-2 aggregation + logits: TWO nodes per warp, inline weights ----------------
__global__ __launch_bounds__(256) void agg2_logits_k(const int* __restrict__ input_y,
                                                     const float* __restrict__ ssw,
                                                     const float* __restrict__ ssb,
                                                     float* __restrict__ out,
                                                     float* __restrict__ mu_out) {
    __shared__ float sw0[N_SAMP], sw1[N_SAMP], sb[N_SAMP];
    for (int i = threadIdx.x; i < N_SAMP / 4; i += blockDim.x) {
        *(float4*)&sw0[i * 4] = *(const float4*)&g_sw0[i * 4];
        *(float4*)&sw1[i * 4] = *(const float4*)&g_sw1[i * 4];
        *(float4*)&sb[i * 4]  = *(const float4*)&g_sb[i * 4];
    }
    __syncthreads();

    int warp = (blockIdx.x * blockDim.x + threadIdx.x) >> 5;
    int lane = threadIdx.x & 31;
    if (warp >= N_NODES / 2) return;
    int v0 = warp * 2, v1 = v0 + 1;
    int b0 = g_off[v0], e0 = g_off[v0 + 1];
    int e1 = g_off[v1 + 1];
    int b1 = e0;
    float edv0 = g_h2e[v0].w;
    float edv1 = g_h2e[v1].w;

    float d0 = 0.f, a00 = 0.f, a01 = 0.f;
    float d1 = 0.f, a10 = 0.f, a11 = 0.f;
    int j0 = b0 + lane, j1 = b1 + lane;
    while (j0 < e0 && j1 < e1) {
        int s0 = g_csr_src[j0];
        int s1 = g_csr_src[j1];
        float4 he0 = g_h2e[s0];
        float4 he1 = g_h2e[s1];
        float w0 = expf(leaky(he0.z + edv0));
        float w1 = expf(leaky(he1.z + edv1));
        d0 += w0; a00 += w0 * he0.x; a01 += w0 * he0.y;
        d1 += w1; a10 += w1 * he1.x; a11 += w1 * he1.y;
        j0 += 32; j1 += 32;
    }
    for (; j0 < e0; j0 += 32) {
        int s = g_csr_src[j0];
        float4 he = g_h2e[s];
        float w = expf(leaky(he.z + edv0));
        d0 += w; a00 += w * he.x; a01 += w * he.y;
    }
    for (; j1 < e1; j1 += 32) {
        int s = g_csr_src[j1];
        float4 he = g_h2e[s];
        float w = expf(leaky(he.z + edv1));
        d1 += w; a10 += w * he.x; a11 += w * he.y;
    }
#pragma unroll
    for (int o = 16; o; o >>= 1) {
        d0  += __shfl_xor_sync(0xffffffffu, d0, o);
        a00 += __shfl_xor_sync(0xffffffffu, a00, o);
        a01 += __shfl_xor_sync(0xffffffffu, a01, o);
        d1  += __shfl_xor_sync(0xffffffffu, d1, o);
        a10 += __shfl_xor_sync(0xffffffffu, a10, o);
        a11 += __shfl_xor_sync(0xffffffffu, a11, o);
    }
    float mu00 = 0.f, mu01 = 0.f, mu10 = 0.f, mu11 = 0.f;
    if (b0 < e0) {
        float inv = 1.f / fmaxf(d0, 1e-16f);
        mu00 = a00 * inv; mu01 = a01 * inv;
    }
    if (b1 < e1) {
        float inv = 1.f / fmaxf(d1, 1e-16f);
        mu10 = a10 * inv; mu11 = a11 * inv;
    }

    float* row0 = out + (size_t)v0 * (N_SAMP + 1);
    float* row1 = out + (size_t)v1 * (N_SAMP + 1);
    if (lane == 0) {
        mu_out[2 * v0] = mu00; mu_out[2 * v0 + 1] = mu01;
        mu_out[2 * v1] = mu10; mu_out[2 * v1 + 1] = mu11;
        int y0 = input_y[v0];
        int y1 = input_y[v1];
        __stcs(&row0[0], mu00 * ssw[2 * y0] + mu01 * ssw[2 * y0 + 1] + ssb[y0]);
        __stcs(&row1[0], mu10 * ssw[2 * y1] + mu11 * ssw[2 * y1 + 1] + ssb[y1]);
    }
    for (int c = lane + 1; c <= N_SAMP; c += 32) {
        int s = c - 1;
        float b = sb[s], s0v = sw0[s], s1v = sw1[s];
        __stcs(&row0[c], mu00 * s0v + mu01 * s1v + b);
        __stcs(&row1[c], mu10 * s0v + mu11 * s1v + b);
    }
}

// ---------------- launch (fork/join: CSR chain overlaps prep+GEMM) ----------------
static cudaStream_t g_s2 = nullptr;
static cudaEvent_t g_ev_fork = nullptr;
static cudaEvent_t g_ev_join = nullptr;

extern "C" void kernel_launch(void* const* d_in, const int* in_sizes, int n_in,
                              void* d_out, int out_size) {
    const float* X         = (const float*)d_in[0];
    const int*   input_y   = (const int*)d_in[2];
    const int*   edge_idx  = (const int*)d_in[3];
    const int*   sample_ids= (const int*)d_in[4];
    const float* W1        = (const float*)d_in[5];
    const float* a1_src    = (const float*)d_in[6];
    const float* a1_dst    = (const float*)d_in[7];
    const float* W_mu      = (const float*)d_in[8];
    const float* amu_src   = (const float*)d_in[9];
    const float* amu_dst   = (const float*)d_in[10];
    const float* ss_weight = (const float*)d_in[14];
    const float* ss_bias   = (const float*)d_in[15];
    float* out = (float*)d_out;

    float* mu_out = out + (size_t)N_NODES * (N_SAMP + 1);

    if (g_s2 == nullptr) {
        cudaStreamCreateWithFlags(&g_s2, cudaStreamNonBlocking);
        cudaEventCreateWithFlags(&g_ev_fork, cudaEventDisableTiming);
        cudaEventCreateWithFlags(&g_ev_join, cudaEventDisableTiming);
    }

    // fork immediately: CSR chain on s2, prep+GEMM on main
    cudaEventRecord(g_ev_fork, 0);
    cudaStreamWaitEvent(g_s2, g_ev_fork, 0);
    zero_counts_k<<<(N_NODES + 255) / 256, 256, 0, g_s2>>>();
    hist_k<<<(N_EDGES / 2 + 255) / 256, 256, 0, g_s2>>>(edge_idx);
    bsum_k<<<SCAN_NB, SCAN_B, 0, g_s2>>>();
    scan_bsums_k<<<1, 512, 0, g_s2>>>();
    write_off_k<<<SCAN_NB, SCAN_B, 0, g_s2>>>();
    fill_k<<<(N_EDGES / 2 + 255) / 256, 256, 0, g_s2>>>(edge_idx);
    cudaEventRecord(g_ev_join, g_s2);

    // main stream: W split + sample gather, then tensor-core GEMM (concurrent with s2)
    prep_k<<<(F_HID * F_IN + 255) / 256, 256>>>(W1, sample_ids, ss_weight, ss_bias);
    gemm_mma_k<<<(N_NODES + 127) / 128, 256>>>(X, a1_src, a1_dst);

    // join, then two-node-per-warp aggregation phases (weights inline, no pre-kernels)
    cudaStreamWaitEvent(0, g_ev_join, 0);
    int pair_blocks = ((N_NODES / 2) * 32 + 255) / 256;   // 6250
    agg1_k<<<pair_blocks, 256>>>(W_mu, amu_src, amu_dst);
    agg2_logits_k<<<pair_blocks, 256>>>(input_y, ss_weight, ss_bias, out, mu_out);
}

// round 14
// speedup vs baseline: 1.0113x; 1.0095x over previous
#include <cuda_runtime.h>
#include <cuda_bf16.h>
#include <cuda_fp16.h>
#include <math.h>
#include <stdint.h>

#define N_NODES 100000
#define N_EDGES 1600000
#define F_IN 256
#define F_HID 128
#define VOCAB 100000
#define N_SAMP 512

#define SCAN_B 256
#define SCAN_NB ((N_NODES + SCAN_B - 1) / SCAN_B)   // 391

// ---------------- scratch (static __device__ — no allocations) ----------------
__device__ uint32_t g_h16[(size_t)N_NODES * (F_HID / 2)];   // h as half2 pairs, 25.6 MB
__device__ float g_es1[N_NODES];
__device__ float g_ed1[N_NODES];
__device__ int   g_counts[N_NODES];
__device__ int   g_off[N_NODES + 1];
__device__ int   g_cursor[N_NODES];
__device__ int   g_csr_src[N_EDGES];
__device__ int   g_csr_dst[N_EDGES];
__device__ float g_w1[N_EDGES];
__device__ float4 g_h2e[N_NODES];           // {h2_0, h2_1, es2, ed2}
__device__ int   g_bsum[SCAN_NB];
__device__ int   g_boff[SCAN_NB];
__device__ __nv_bfloat16 g_Bt_hi[F_HID * F_IN];
__device__ __nv_bfloat16 g_Bt_lo[F_HID * F_IN];
__device__ float g_sw0[N_SAMP];
__device__ float g_sw1[N_SAMP];
__device__ float g_sb[N_SAMP];

// ---------------- s2 branch: zero counts ----------------
__global__ void zero_counts_k() {
    int i = blockIdx.x * blockDim.x + threadIdx.x;
    if (i < N_NODES) g_counts[i] = 0;
}

// ---------------- main branch: W1 split + sample-table gather ----------------
__global__ void prep_k(const float* __restrict__ W1,
                       const int* __restrict__ sample_ids,
                       const float* __restrict__ ssw,
                       const float* __restrict__ ssb) {
    int i = blockIdx.x * blockDim.x + threadIdx.x;
    if (i < F_HID * F_IN) {
        int n = i / F_IN;
        int k = i % F_IN;
        float w = W1[(size_t)k * F_HID + n];
        __nv_bfloat16 hi = __float2bfloat16(w);
        float r = w - __bfloat162float(hi);
        g_Bt_hi[i] = hi;
        g_Bt_lo[i] = __float2bfloat16(r);
    }
    if (i < N_SAMP) {
        int sid = sample_ids[i];
        g_sw0[i] = ssw[2 * sid];
        g_sw1[i] = ssw[2 * sid + 1];
        g_sb[i] = ssb[sid];
    }
}

// ---------------- CSR build (vectorized 2 edges/thread) ----------------
__global__ void hist_k(const int* __restrict__ edge_index) {
    int t = blockIdx.x * blockDim.x + threadIdx.x;
    int e = t * 2;
    if (e < N_EDGES) {
        int2 d = *(const int2*)(edge_index + N_EDGES + e);
        atomicAdd(&g_counts[d.x], 1);
        atomicAdd(&g_counts[d.y], 1);
    }
}

__global__ __launch_bounds__(SCAN_B) void bsum_k() {
    int i = blockIdx.x * SCAN_B + threadIdx.x;
    int c = (i < N_NODES) ? g_counts[i] : 0;
#pragma unroll
    for (int o = 16; o; o >>= 1) c += __shfl_xor_sync(0xffffffffu, c, o);
    __shared__ int ws[SCAN_B / 32];
    if ((threadIdx.x & 31) == 0) ws[threadIdx.x >> 5] = c;
    __syncthreads();
    if (threadIdx.x < SCAN_B / 32) {
        int v = ws[threadIdx.x];
#pragma unroll
        for (int o = SCAN_B / 64; o; o >>= 1) v += __shfl_xor_sync(0xffffffffu, v, o);
        if (threadIdx.x == 0) g_bsum[blockIdx.x] = v;
    }
}

__global__ __launch_bounds__(512) void scan_bsums_k() {
    __shared__ int s[512];
    int t = threadIdx.x;
    int v = (t < SCAN_NB) ? g_bsum[t] : 0;
    s[t] = v;
    __syncthreads();
    for (int d = 1; d < 512; d <<= 1) {
        int x = 0;
        if (t >= d) x = s[t - d];
        __syncthreads();
        s[t] += x;
        __syncthreads();
    }
    if (t < SCAN_NB) g_boff[t] = s[t] - v;
    if (t == 511) g_off[N_NODES] = s[SCAN_NB - 1];
}

__global__ __launch_bounds__(SCAN_B) void write_off_k() {
    int i = blockIdx.x * SCAN_B + threadIdx.x;
    int lane = threadIdx.x & 31;
    int wid = threadIdx.x >> 5;
    int c = (i < N_NODES) ? g_counts[i] : 0;
    int inc = c;
#pragma unroll
    for (int d = 1; d < 32; d <<= 1) {
        int x = __shfl_up_sync(0xffffffffu, inc, d);
        if (lane >= d) inc += x;
    }
    __shared__ int wsum[SCAN_B / 32];
    if (lane == 31) wsum[wid] = inc;
    __syncthreads();
    if (threadIdx.x == 0) {
        int run = 0;
#pragma unroll
        for (int wv = 0; wv < SCAN_B / 32; wv++) {
            int x = wsum[wv];
            wsum[wv] = run;
            run += x;
        }
    }
    __syncthreads();
    int off = g_boff[blockIdx.x] + wsum[wid] + inc - c;
    if (i < N_NODES) {
        g_off[i] = off;
        g_cursor[i] = off;
    }
}

__global__ void fill_k(const int* __restrict__ edge_index) {
    int t = blockIdx.x * blockDim.x + threadIdx.x;
    int e = t * 2;
    if (e < N_EDGES) {
        int2 s = *(const int2*)(edge_index + e);
        int2 d = *(const int2*)(edge_index + N_EDGES + e);
        int p0 = atomicAdd(&g_cursor[d.x], 1);
        g_csr_src[p0] = s.x;
        g_csr_dst[p0] = d.x;
        int p1 = atomicAdd(&g_cursor[d.y], 1);
        g_csr_src[p1] = s.y;
        g_csr_dst[p1] = d.y;
    }
}

// ---------------- tensor-core GEMM + fused attention-dot epilogue (h -> fp16) ----------------
#define SMEM_STRIDE 40

__device__ __forceinline__ void mma16816(float* d,
                                         uint32_t a0, uint32_t a1, uint32_t a2, uint32_t a3,
                                         uint32_t b0, uint32_t b1) {
    asm volatile(
        "mma.sync.aligned.m16n8k16.row.col.f32.bf16.bf16.f32 "
        "{%0,%1,%2,%3}, {%4,%5,%6,%7}, {%8,%9}, {%0,%1,%2,%3};\n"
        : "+f"(d[0]), "+f"(d[1]), "+f"(d[2]), "+f"(d[3])
        : "r"(a0), "r"(a1), "r"(a2), "r"(a3), "r"(b0), "r"(b1));
}

__global__ __launch_bounds__(256) void gemm_mma_k(const float* __restrict__ A,
                                                  const float* __restrict__ a1_src,
                                                  const float* __restrict__ a1_dst) {
    __shared__ __nv_bfloat16 As_hi[128][SMEM_STRIDE];
    __shared__ __nv_bfloat16 As_lo[128][SMEM_STRIDE];
    __shared__ __nv_bfloat16 Bs_hi[128][SMEM_STRIDE];
    __shared__ __nv_bfloat16 Bs_lo[128][SMEM_STRIDE];
    __shared__ float es_s[128][2], ed_s[128][2];

    const int tid = threadIdx.x;
    const int block_row = blockIdx.x * 128;
    const int w = tid >> 5, l = tid & 31;
    const int warp_m = (w >> 1) * 32;
    const int warp_n = (w & 1) * 64;
    const int nhalf = w & 1;

    float acc[2][8][4];
#pragma unroll
    for (int i = 0; i < 2; i++)
#pragma unroll
        for (int j = 0; j < 8; j++)
#pragma unroll
            for (int q = 0; q < 4; q++) acc[i][j][q] = 0.f;

    const int ar = tid >> 1;
    const int ac = (tid & 1) * 16;

    for (int k0 = 0; k0 < F_IN; k0 += 32) {
        {
            int gr = block_row + ar;
#pragma unroll
            for (int j = 0; j < 4; j++) {
                float4 v = make_float4(0.f, 0.f, 0.f, 0.f);
                if (gr < N_NODES)
                    v = *(const float4*)(A + (size_t)gr * F_IN + k0 + ac + j * 4);
                float xs[4] = {v.x, v.y, v.z, v.w};
                __nv_bfloat16 hi[4], lo[4];
#pragma unroll
                for (int c = 0; c < 4; c++) {
                    hi[c] = __float2bfloat16(xs[c]);
                    lo[c] = __float2bfloat16(xs[c] - __bfloat162float(hi[c]));
                }
                __nv_bfloat162* ph = (__nv_bfloat162*)&As_hi[ar][ac + j * 4];
                __nv_bfloat162* pl = (__nv_bfloat162*)&As_lo[ar][ac + j * 4];
                ph[0] = __nv_bfloat162(hi[0], hi[1]);
                ph[1] = __nv_bfloat162(hi[2], hi[3]);
                pl[0] = __nv_bfloat162(lo[0], lo[1]);
                pl[1] = __nv_bfloat162(lo[2], lo[3]);
            }
        }
        {
            const __nv_bfloat16* bh = g_Bt_hi + (size_t)ar * F_IN + k0 + ac;
            const __nv_bfloat16* bl = g_Bt_lo + (size_t)ar * F_IN + k0 + ac;
            *(uint4*)&Bs_hi[ar][ac] = *(const uint4*)bh;
            *(uint4*)&Bs_hi[ar][ac + 8] = *(const uint4*)(bh + 8);
            *(uint4*)&Bs_lo[ar][ac] = *(const uint4*)bl;
            *(uint4*)&Bs_lo[ar][ac + 8] = *(const uint4*)(bl + 8);
        }
        __syncthreads();

#pragma unroll
        for (int ks = 0; ks < 32; ks += 16) {
            const int fr = l >> 2;
            const int fc = ks + (l & 3) * 2;
            uint32_t ah[2][4], al[2][4];
#pragma unroll
            for (int mf = 0; mf < 2; mf++) {
                int r = warp_m + mf * 16 + fr;
                ah[mf][0] = *(const uint32_t*)&As_hi[r][fc];
                ah[mf][1] = *(const uint32_t*)&As_hi[r + 8][fc];
                ah[mf][2] = *(const uint32_t*)&As_hi[r][fc + 8];
                ah[mf][3] = *(const uint32_t*)&As_hi[r + 8][fc + 8];
                al[mf][0] = *(const uint32_t*)&As_lo[r][fc];
                al[mf][1] = *(const uint32_t*)&As_lo[r + 8][fc];
                al[mf][2] = *(const uint32_t*)&As_lo[r][fc + 8];
                al[mf][3] = *(const uint32_t*)&As_lo[r + 8][fc + 8];
            }
#pragma unroll
            for (int nf = 0; nf < 8; nf++) {
                int n = warp_n + nf * 8 + fr;
                uint32_t bh0 = *(const uint32_t*)&Bs_hi[n][fc];
                uint32_t bh1 = *(const uint32_t*)&Bs_hi[n][fc + 8];
                uint32_t bl0 = *(const uint32_t*)&Bs_lo[n][fc];
                uint32_t bl1 = *(const uint32_t*)&Bs_lo[n][fc + 8];
#pragma unroll
                for (int mf = 0; mf < 2; mf++) {
                    mma16816(acc[mf][nf], ah[mf][0], ah[mf][1], ah[mf][2], ah[mf][3], bh0, bh1);
                    mma16816(acc[mf][nf], ah[mf][0], ah[mf][1], ah[mf][2], ah[mf][3], bl0, bl1);
                    mma16816(acc[mf][nf], al[mf][0], al[mf][1], al[mf][2], al[mf][3], bh0, bh1);
                }
            }
        }
        __syncthreads();
    }

    const int fr = l >> 2;
    const int quad = l & 3;

#pragma unroll
    for (int mf = 0; mf < 2; mf++) {
        int rl0 = warp_m + mf * 16 + fr;
        int rl1 = rl0 + 8;
        int r0 = block_row + rl0;
        int r1 = block_row + rl1;
        float es0 = 0.f, ed0 = 0.f, es1 = 0.f, ed1 = 0.f;
#pragma unroll
        for (int nf = 0; nf < 8; nf++) {
            int cc = warp_n + nf * 8 + quad * 2;
            float as0 = a1_src[cc], as1 = a1_src[cc + 1];
            float ad0 = a1_dst[cc], ad1 = a1_dst[cc + 1];
            es0 += acc[mf][nf][0] * as0 + acc[mf][nf][1] * as1;
            ed0 += acc[mf][nf][0] * ad0 + acc[mf][nf][1] * ad1;
            es1 += acc[mf][nf][2] * as0 + acc[mf][nf][3] * as1;
            ed1 += acc[mf][nf][2] * ad0 + acc[mf][nf][3] * ad1;
            if (r0 < N_NODES) {
                __half2 hv = __floats2half2_rn(acc[mf][nf][0], acc[mf][nf][1]);
                g_h16[(size_t)r0 * (F_HID / 2) + (cc >> 1)] = *(uint32_t*)&hv;
            }
            if (r1 < N_NODES) {
                __half2 hv = __floats2half2_rn(acc[mf][nf][2], acc[mf][nf][3]);
                g_h16[(size_t)r1 * (F_HID / 2) + (cc >> 1)] = *(uint32_t*)&hv;
            }
        }
#pragma unroll
        for (int o = 1; o <= 2; o <<= 1) {
            es0 += __shfl_xor_sync(0xffffffffu, es0, o);
            ed0 += __shfl_xor_sync(0xffffffffu, ed0, o);
            es1 += __shfl_xor_sync(0xffffffffu, es1, o);
            ed1 += __shfl_xor_sync(0xffffffffu, ed1, o);
        }
        if (quad == 0) {
            es_s[rl0][nhalf] = es0;
            ed_s[rl0][nhalf] = ed0;
            es_s[rl1][nhalf] = es1;
            ed_s[rl1][nhalf] = ed1;
        }
    }
    __syncthreads();
    if (tid < 128) {
        int gr = block_row + tid;
        if (gr < N_NODES) {
            g_es1[gr] = es_s[tid][0] + es_s[tid][1];
            g_ed1[gr] = ed_s[tid][0] + ed_s[tid][1];
        }
    }
}

__device__ __forceinline__ float leaky(float x) { return x > 0.f ? x : 0.2f * x; }

// ---------------- edge-parallel weight precompute, layer 1 ----------------
__global__ void w1_pre_k() {
    int j = blockIdx.x * blockDim.x + threadIdx.x;
    if (j < N_EDGES) {
        int s = g_csr_src[j];
        int d = g_csr_dst[j];
        g_w1[j] = expf(leaky(g_es1[s] + g_ed1[d]));
    }
}

// ---------------- layer-1 aggregation: 2 nodes x 4 edges per warp iteration ----------------
__global__ __launch_bounds__(256) void agg1_k(const float* __restrict__ Wmu,
                                              const float* __restrict__ amus,
                                              const float* __restrict__ amud) {
    int warp = (blockIdx.x * blockDim.x + threadIdx.x) >> 5;
    int lane = threadIdx.x & 31;
    if (warp >= N_NODES / 2) return;
    int v0 = warp * 2, v1 = v0 + 1;
    int b0 = g_off[v0], e0 = g_off[v0 + 1];
    int e1 = g_off[v1 + 1];
    int b1 = e0;

    float A00 = 0.f, A01 = 0.f, A02 = 0.f, A03 = 0.f, D0 = 0.f;
    float A10 = 0.f, A11 = 0.f, A12 = 0.f, A13 = 0.f, D1 = 0.f;

    int j0 = b0, j1 = b1;
    // main interleaved loop: 4 edges per node per iteration (8 independent gather chains)
    while (j0 + 4 <= e0 && j1 + 4 <= e1) {
        int s00 = g_csr_src[j0],     s01 = g_csr_src[j0 + 1];
        int s02 = g_csr_src[j0 + 2], s03 = g_csr_src[j0 + 3];
        int s10 = g_csr_src[j1],     s11 = g_csr_src[j1 + 1];
        int s12 = g_csr_src[j1 + 2], s13 = g_csr_src[j1 + 3];
        float w00 = g_w1[j0],     w01 = g_w1[j0 + 1];
        float w02 = g_w1[j0 + 2], w03 = g_w1[j0 + 3];
        float w10 = g_w1[j1],     w11 = g_w1[j1 + 1];
        float w12 = g_w1[j1 + 2], w13 = g_w1[j1 + 3];
        const uint32_t* p00 = g_h16 + (size_t)s00 * (F_HID / 2);
        const uint32_t* p01 = g_h16 + (size_t)s01 * (F_HID / 2);
        const uint32_t* p02 = g_h16 + (size_t)s02 * (F_HID / 2);
        const uint32_t* p03 = g_h16 + (size_t)s03 * (F_HID / 2);
        const uint32_t* p10 = g_h16 + (size_t)s10 * (F_HID / 2);
        const uint32_t* p11 = g_h16 + (size_t)s11 * (F_HID / 2);
        const uint32_t* p12 = g_h16 + (size_t)s12 * (F_HID / 2);
        const uint32_t* p13 = g_h16 + (size_t)s13 * (F_HID / 2);
        uint32_t q00a = p00[lane], q00b = p00[lane + 32];
        uint32_t q01a = p01[lane], q01b = p01[lane + 32];
        uint32_t q02a = p02[lane], q02b = p02[lane + 32];
        uint32_t q03a = p03[lane], q03b = p03[lane + 32];
        uint32_t q10a = p10[lane], q10b = p10[lane + 32];
        uint32_t q11a = p11[lane], q11b = p11[lane + 32];
        uint32_t q12a = p12[lane], q12b = p12[lane + 32];
        uint32_t q13a = p13[lane], q13b = p13[lane + 32];
        float2 x00a = __half22float2(*(__half2*)&q00a), x00b = __half22float2(*(__half2*)&q00b);
        float2 x01a = __half22float2(*(__half2*)&q01a), x01b = __half22float2(*(__half2*)&q01b);
        float2 x02a = __half22float2(*(__half2*)&q02a), x02b = __half22float2(*(__half2*)&q02b);
        float2 x03a = __half22float2(*(__half2*)&q03a), x03b = __half22float2(*(__half2*)&q03b);
        float2 x10a = __half22float2(*(__half2*)&q10a), x10b = __half22float2(*(__half2*)&q10b);
        float2 x11a = __half22float2(*(__half2*)&q11a), x11b = __half22float2(*(__half2*)&q11b);
        float2 x12a = __half22float2(*(__half2*)&q12a), x12b = __half22float2(*(__half2*)&q12b);
        float2 x13a = __half22float2(*(__half2*)&q13a), x13b = __half22float2(*(__half2*)&q13b);
        D0 += (w00 + w01) + (w02 + w03);
        A00 += w00 * x00a.x + w01 * x01a.x + w02 * x02a.x + w03 * x03a.x;
        A01 += w00 * x00a.y + w01 * x01a.y + w02 * x02a.y + w03 * x03a.y;
        A02 += w00 * x00b.x + w01 * x01b.x + w02 * x02b.x + w03 * x03b.x;
        A03 += w00 * x00b.y + w01 * x01b.y + w02 * x02b.y + w03 * x03b.y;
        D1 += (w10 + w11) + (w12 + w13);
        A10 += w10 * x10a.x + w11 * x11a.x + w12 * x12a.x + w13 * x13a.x;
        A11 += w10 * x10a.y + w11 * x11a.y + w12 * x12a.y + w13 * x13a.y;
        A12 += w10 * x10b.x + w11 * x11b.x + w12 * x12b.x + w13 * x13b.x;
        A13 += w10 * x10b.y + w11 * x11b.y + w12 * x12b.y + w13 * x13b.y;
        j0 += 4;
        j1 += 4;
    }
    // drains
    for (; j0 < e0; j0++) {
        int s = g_csr_src[j0];
        float wg = g_w1[j0];
        const uint32_t* p = g_h16 + (size_t)s * (F_HID / 2);
        uint32_t qa = p[lane], qb = p[lane + 32];
        float2 xa = __half22float2(*(__half2*)&qa), xb = __half22float2(*(__half2*)&qb);
        D0 += wg;
        A00 += wg * xa.x;
        A01 += wg * xa.y;
        A02 += wg * xb.x;
        A03 += wg * xb.y;
    }
    for (; j1 < e1; j1++) {
        int s = g_csr_src[j1];
        float wg = g_w1[j1];
        const uint32_t* p = g_h16 + (size_t)s * (F_HID / 2);
        uint32_t qa = p[lane], qb = p[lane + 32];
        float2 xa = __half22float2(*(__half2*)&qa), xb = __half22float2(*(__half2*)&qb);
        D1 += wg;
        A10 += wg * xa.x;
        A11 += wg * xa.y;
        A12 += wg * xb.x;
        A13 += wg * xb.y;
    }

    // epilogue for both nodes
    int f0 = 2 * lane, f1 = 2 * lane + 1, f2 = 64 + 2 * lane, f3 = 64 + 2 * lane + 1;
    float Wm00 = Wmu[f0 * 2], Wm01 = Wmu[f0 * 2 + 1];
    float Wm10 = Wmu[f1 * 2], Wm11 = Wmu[f1 * 2 + 1];
    float Wm20 = Wmu[f2 * 2], Wm21 = Wmu[f2 * 2 + 1];
    float Wm30 = Wmu[f3 * 2], Wm31 = Wmu[f3 * 2 + 1];

    float h00 = 0.f, h01 = 0.f, h10 = 0.f, h11 = 0.f;
    if (b0 < e0) {
        float inv = 1.f / fmaxf(D0, 1e-16f);
        float a0 = fmaxf(A00 * inv, 0.f), a1 = fmaxf(A01 * inv, 0.f);
        float a2 = fmaxf(A02 * inv, 0.f), a3 = fmaxf(A03 * inv, 0.f);
        h00 = a0 * Wm00 + a1 * Wm10 + a2 * Wm20 + a3 * Wm30;
        h01 = a0 * Wm01 + a1 * Wm11 + a2 * Wm21 + a3 * Wm31;
    }
    if (b1 < e1) {
        float inv = 1.f / fmaxf(D1, 1e-16f);
        float a0 = fmaxf(A10 * inv, 0.f), a1 = fmaxf(A11 * inv, 0.f);
        float a2 = fmaxf(A12 * inv, 0.f), a3 = fmaxf(A13 * inv, 0.f);
        h10 = a0 * Wm00 + a1 * Wm10 + a2 * Wm20 + a3 * Wm30;
        h11 = a0 * Wm01 + a1 * Wm11 + a2 * Wm21 + a3 * Wm31;
    }
#pragma unroll
    for (int o = 16; o; o >>= 1) {
        h00 += __shfl_xor_sync(0xffffffffu, h00, o);
        h01 += __shfl_xor_sync(0xffffffffu, h01, o);
        h10 += __shfl_xor_sync(0xffffffffu, h10, o);
        h11 += __shfl_xor_sync(0xffffffffu, h11, o);
    }
    if (lane == 0) {
        float as0 = amus[0], as1 = amus[1], ad0 = amud[0], ad1 = amud[1];
        g_h2e[v0] = make_float4(h00, h01, h00 * as0 + h01 * as1, h00 * ad0 + h01 * ad1);
        g_h2e[v1] = make_float4(h10, h11, h10 * as0 + h11 * as1, h10 * ad0 + h11 * ad1);
    }
}

// ---------------- layer-2 aggregation + logits: TWO nodes per warp, inline weights ----------------
__global__ __launch_bounds__(256) void agg2_logits_k(const int* __restrict__ input_y,
                                                     const float* __restrict__ ssw,
                                                     const float* __restrict__ ssb,
                                                     float* __restrict__ out,
                                                     float* __restrict__ mu_out) {
    __shared__ float sw0[N_SAMP], sw1[N_SAMP], sb[N_SAMP];
    for (int i = threadIdx.x; i < N_SAMP / 4; i += blockDim.x) {
        *(float4*)&sw0[i * 4] = *(const float4*)&g_sw0[i * 4];
        *(float4*)&sw1[i * 4] = *(const float4*)&g_sw1[i * 4];
        *(float4*)&sb[i * 4]  = *(const float4*)&g_sb[i * 4];
    }
    __syncthreads();

    int warp = (blockIdx.x * blockDim.x + threadIdx.x) >> 5;
    int lane = threadIdx.x & 31;
    if (warp >= N_NODES / 2) return;
    int v0 = warp * 2, v1 = v0 + 1;
    int b0 = g_off[v0], e0 = g_off[v0 + 1];
    int e1 = g_off[v1 + 1];
    int b1 = e0;
    float edv0 = g_h2e[v0].w;
    float edv1 = g_h2e[v1].w;

    float d0 = 0.f, a00 = 0.f, a01 = 0.f;
    float d1 = 0.f, a10 = 0.f, a11 = 0.f;
    int j0 = b0 + lane, j1 = b1 + lane;
    while (j0 < e0 && j1 < e1) {
        int s0 = g_csr_src[j0];
        int s1 = g_csr_src[j1];
        float4 he0 = g_h2e[s0];
        float4 he1 = g_h2e[s1];
        float w0 = expf(leaky(he0.z + edv0));
        float w1 = expf(leaky(he1.z + edv1));
        d0 += w0; a00 += w0 * he0.x; a01 += w0 * he0.y;
        d1 += w1; a10 += w1 * he1.x; a11 += w1 * he1.y;
        j0 += 32; j1 += 32;
    }
    for (; j0 < e0; j0 += 32) {
        int s = g_csr_src[j0];
        float4 he = g_h2e[s];
        float w = expf(leaky(he.z + edv0));
        d0 += w; a00 += w * he.x; a01 += w * he.y;
    }
    for (; j1 < e1; j1 += 32) {
        int s = g_csr_src[j1];
        float4 he = g_h2e[s];
        float w = expf(leaky(he.z + edv1));
        d1 += w; a10 += w * he.x; a11 += w * he.y;
    }
#pragma unroll
    for (int o = 16; o; o >>= 1) {
        d0  += __shfl_xor_sync(0xffffffffu, d0, o);
        a00 += __shfl_xor_sync(0xffffffffu, a00, o);
        a01 += __shfl_xor_sync(0xffffffffu, a01, o);
        d1  += __shfl_xor_sync(0xffffffffu, d1, o);
        a10 += __shfl_xor_sync(0xffffffffu, a10, o);
        a11 += __shfl_xor_sync(0xffffffffu, a11, o);
    }
    float mu00 = 0.f, mu01 = 0.f, mu10 = 0.f, mu11 = 0.f;
    if (b0 < e0) {
        float inv = 1.f / fmaxf(d0, 1e-16f);
        mu00 = a00 * inv; mu01 = a01 * inv;
    }
    if (b1 < e1) {
        float inv = 1.f / fmaxf(d1, 1e-16f);
        mu10 = a10 * inv; mu11 = a11 * inv;
    }

    float* row0 = out + (size_t)v0 * (N_SAMP + 1);
    float* row1 = out + (size_t)v1 * (N_SAMP + 1);
    if (lane == 0) {
        mu_out[2 * v0] = mu00; mu_out[2 * v0 + 1] = mu01;
        mu_out[2 * v1] = mu10; mu_out[2 * v1 + 1] = mu11;
        int y0 = input_y[v0];
        int y1 = input_y[v1];
        __stcs(&row0[0], mu00 * ssw[2 * y0] + mu01 * ssw[2 * y0 + 1] + ssb[y0]);
        __stcs(&row1[0], mu10 * ssw[2 * y1] + mu11 * ssw[2 * y1 + 1] + ssb[y1]);
    }
    for (int c = lane + 1; c <= N_SAMP; c += 32) {
        int s = c - 1;
        float b = sb[s], s0v = sw0[s], s1v = sw1[s];
        __stcs(&row0[c], mu00 * s0v + mu01 * s1v + b);
        __stcs(&row1[c], mu10 * s0v + mu11 * s1v + b);
    }
}

// ---------------- launch (fork/join: CSR chain overlaps prep+GEMM) ----------------
static cudaStream_t g_s2 = nullptr;
static cudaEvent_t g_ev_fork = nullptr;
static cudaEvent_t g_ev_join = nullptr;

extern "C" void kernel_launch(void* const* d_in, const int* in_sizes, int n_in,
                              void* d_out, int out_size) {
    const float* X         = (const float*)d_in[0];
    const int*   input_y   = (const int*)d_in[2];
    const int*   edge_idx  = (const int*)d_in[3];
    const int*   sample_ids= (const int*)d_in[4];
    const float* W1        = (const float*)d_in[5];
    const float* a1_src    = (const float*)d_in[6];
    const float* a1_dst    = (const float*)d_in[7];
    const float* W_mu      = (const float*)d_in[8];
    const float* amu_src   = (const float*)d_in[9];
    const float* amu_dst   = (const float*)d_in[10];
    const float* ss_weight = (const float*)d_in[14];
    const float* ss_bias   = (const float*)d_in[15];
    float* out = (float*)d_out;

    float* mu_out = out + (size_t)N_NODES * (N_SAMP + 1);

    if (g_s2 == nullptr) {
        cudaStreamCreateWithFlags(&g_s2, cudaStreamNonBlocking);
        cudaEventCreateWithFlags(&g_ev_fork, cudaEventDisableTiming);
        cudaEventCreateWithFlags(&g_ev_join, cudaEventDisableTiming);
    }

    // fork immediately: CSR chain on s2, prep+GEMM on main
    cudaEventRecord(g_ev_fork, 0);
    cudaStreamWaitEvent(g_s2, g_ev_fork, 0);
    zero_counts_k<<<(N_NODES + 255) / 256, 256, 0, g_s2>>>();
    hist_k<<<(N_EDGES / 2 + 255) / 256, 256, 0, g_s2>>>(edge_idx);
    bsum_k<<<SCAN_NB, SCAN_B, 0, g_s2>>>();
    scan_bsums_k<<<1, 512, 0, g_s2>>>();
    write_off_k<<<SCAN_NB, SCAN_B, 0, g_s2>>>();
    fill_k<<<(N_EDGES / 2 + 255) / 256, 256, 0, g_s2>>>(edge_idx);
    cudaEventRecord(g_ev_join, g_s2);

    // main stream: W split + sample gather, then tensor-core GEMM (concurrent with s2)
    prep_k<<<(F_HID * F_IN + 255) / 256, 256>>>(W1, sample_ids, ss_weight, ss_bias);
    gemm_mma_k<<<(N_NODES + 127) / 128, 256>>>(X, a1_src, a1_dst);

    // join, then w1 precompute + aggregation phases
    cudaStreamWaitEvent(0, g_ev_join, 0);
    int edge_blocks = (N_EDGES + 255) / 256;
    int pair_blocks = ((N_NODES / 2) * 32 + 255) / 256;   // 6250
    w1_pre_k<<<edge_blocks, 256>>>();
    agg1_k<<<pair_blocks, 256>>>(W_mu, amu_src, amu_dst);
    agg2_logits_k<<<pair_blocks, 256>>>(input_y, ss_weight, ss_bias, out, mu_out);
}

// round 15
// speedup vs baseline: 1.0704x; 1.0584x over previous
#include <cuda_runtime.h>
#include <cuda_bf16.h>
#include <cuda_fp16.h>
#include <math.h>
#include <stdint.h>

#define N_NODES 100000
#define N_EDGES 1600000
#define F_IN 256
#define F_HID 128
#define VOCAB 100000
#define N_SAMP 512

#define SCAN_B 256
#define SCAN_NB ((N_NODES + SCAN_B - 1) / SCAN_B)   // 391

// ---------------- scratch (static __device__ — no allocations) ----------------
__device__ uint32_t g_h16[(size_t)N_NODES * (F_HID / 2)];   // h as half2 pairs, 25.6 MB
__device__ float g_es1[N_NODES];
__device__ float g_ed1[N_NODES];
__device__ int   g_counts[N_NODES];
__device__ int   g_off[N_NODES + 1];
__device__ int   g_cursor[N_NODES];
__device__ int   g_csr_src[N_EDGES];
__device__ int   g_csr_dst[N_EDGES];
__device__ float g_w1[N_EDGES];
__device__ float4 g_h2e[N_NODES];           // {h2_0, h2_1, es2, ed2}
__device__ int   g_bsum[SCAN_NB];
__device__ int   g_boff[SCAN_NB];
__device__ __nv_bfloat16 g_Bt_hi[F_HID * F_IN];
__device__ __nv_bfloat16 g_Bt_lo[F_HID * F_IN];
__device__ float g_sw0[N_SAMP];
__device__ float g_sw1[N_SAMP];
__device__ float g_sb[N_SAMP];

// ---------------- s2 branch: zero counts ----------------
__global__ void zero_counts_k() {
    int i = blockIdx.x * blockDim.x + threadIdx.x;
    if (i < N_NODES) g_counts[i] = 0;
}

// ---------------- main branch: W1 split + sample-table gather ----------------
__global__ void prep_k(const float* __restrict__ W1,
                       const int* __restrict__ sample_ids,
                       const float* __restrict__ ssw,
                       const float* __restrict__ ssb) {
    int i = blockIdx.x * blockDim.x + threadIdx.x;
    if (i < F_HID * F_IN) {
        int n = i / F_IN;
        int k = i % F_IN;
        float w = W1[(size_t)k * F_HID + n];
        __nv_bfloat16 hi = __float2bfloat16(w);
        float r = w - __bfloat162float(hi);
        g_Bt_hi[i] = hi;
        g_Bt_lo[i] = __float2bfloat16(r);
    }
    if (i < N_SAMP) {
        int sid = sample_ids[i];
        g_sw0[i] = ssw[2 * sid];
        g_sw1[i] = ssw[2 * sid + 1];
        g_sb[i] = ssb[sid];
    }
}

// ---------------- CSR build (vectorized 4 edges/thread) ----------------
__global__ void hist_k(const int* __restrict__ edge_index) {
    int t = blockIdx.x * blockDim.x + threadIdx.x;
    int e = t * 4;
    if (e < N_EDGES) {
        int4 d = *(const int4*)(edge_index + N_EDGES + e);
        atomicAdd(&g_counts[d.x], 1);
        atomicAdd(&g_counts[d.y], 1);
        atomicAdd(&g_counts[d.z], 1);
        atomicAdd(&g_counts[d.w], 1);
    }
}

__global__ __launch_bounds__(SCAN_B) void bsum_k() {
    int i = blockIdx.x * SCAN_B + threadIdx.x;
    int c = (i < N_NODES) ? g_counts[i] : 0;
#pragma unroll
    for (int o = 16; o; o >>= 1) c += __shfl_xor_sync(0xffffffffu, c, o);
    __shared__ int ws[SCAN_B / 32];
    if ((threadIdx.x & 31) == 0) ws[threadIdx.x >> 5] = c;
    __syncthreads();
    if (threadIdx.x < SCAN_B / 32) {
        int v = ws[threadIdx.x];
#pragma unroll
        for (int o = SCAN_B / 64; o; o >>= 1) v += __shfl_xor_sync(0xffffffffu, v, o);
        if (threadIdx.x == 0) g_bsum[blockIdx.x] = v;
    }
}

__global__ __launch_bounds__(512) void scan_bsums_k() {
    __shared__ int s[512];
    int t = threadIdx.x;
    int v = (t < SCAN_NB) ? g_bsum[t] : 0;
    s[t] = v;
    __syncthreads();
    for (int d = 1; d < 512; d <<= 1) {
        int x = 0;
        if (t >= d) x = s[t - d];
        __syncthreads();
        s[t] += x;
        __syncthreads();
    }
    if (t < SCAN_NB) g_boff[t] = s[t] - v;
    if (t == 511) g_off[N_NODES] = s[SCAN_NB - 1];
}

__global__ __launch_bounds__(SCAN_B) void write_off_k() {
    int i = blockIdx.x * SCAN_B + threadIdx.x;
    int lane = threadIdx.x & 31;
    int wid = threadIdx.x >> 5;
    int c = (i < N_NODES) ? g_counts[i] : 0;
    int inc = c;
#pragma unroll
    for (int d = 1; d < 32; d <<= 1) {
        int x = __shfl_up_sync(0xffffffffu, inc, d);
        if (lane >= d) inc += x;
    }
    __shared__ int wsum[SCAN_B / 32];
    if (lane == 31) wsum[wid] = inc;
    __syncthreads();
    if (threadIdx.x == 0) {
        int run = 0;
#pragma unroll
        for (int wv = 0; wv < SCAN_B / 32; wv++) {
            int x = wsum[wv];
            wsum[wv] = run;
            run += x;
        }
    }
    __syncthreads();
    int off = g_boff[blockIdx.x] + wsum[wid] + inc - c;
    if (i < N_NODES) {
        g_off[i] = off;
        g_cursor[i] = off;
    }
}

__global__ void fill_k(const int* __restrict__ edge_index) {
    int t = blockIdx.x * blockDim.x + threadIdx.x;
    int e = t * 4;
    if (e < N_EDGES) {
        int4 s = *(const int4*)(edge_index + e);
        int4 d = *(const int4*)(edge_index + N_EDGES + e);
        int p0 = atomicAdd(&g_cursor[d.x], 1);
        g_csr_src[p0] = s.x; g_csr_dst[p0] = d.x;
        int p1 = atomicAdd(&g_cursor[d.y], 1);
        g_csr_src[p1] = s.y; g_csr_dst[p1] = d.y;
        int p2 = atomicAdd(&g_cursor[d.z], 1);
        g_csr_src[p2] = s.z; g_csr_dst[p2] = d.z;
        int p3 = atomicAdd(&g_cursor[d.w], 1);
        g_csr_src[p3] = s.w; g_csr_dst[p3] = d.w;
    }
}

// ---------------- tensor-core GEMM (A-prefetch pipelined) + fused dot epilogue ----------------
#define SMEM_STRIDE 40

__device__ __forceinline__ void mma16816(float* d,
                                         uint32_t a0, uint32_t a1, uint32_t a2, uint32_t a3,
                                         uint32_t b0, uint32_t b1) {
    asm volatile(
        "mma.sync.aligned.m16n8k16.row.col.f32.bf16.bf16.f32 "
        "{%0,%1,%2,%3}, {%4,%5,%6,%7}, {%8,%9}, {%0,%1,%2,%3};\n"
        : "+f"(d[0]), "+f"(d[1]), "+f"(d[2]), "+f"(d[3])
        : "r"(a0), "r"(a1), "r"(a2), "r"(a3), "r"(b0), "r"(b1));
}

__global__ __launch_bounds__(256) void gemm_mma_k(const float* __restrict__ A,
                                                  const float* __restrict__ a1_src,
                                                  const float* __restrict__ a1_dst) {
    __shared__ __nv_bfloat16 As_hi[128][SMEM_STRIDE];
    __shared__ __nv_bfloat16 As_lo[128][SMEM_STRIDE];
    __shared__ __nv_bfloat16 Bs_hi[128][SMEM_STRIDE];
    __shared__ __nv_bfloat16 Bs_lo[128][SMEM_STRIDE];
    __shared__ float es_s[128][2], ed_s[128][2];

    const int tid = threadIdx.x;
    const int block_row = blockIdx.x * 128;
    const int w = tid >> 5, l = tid & 31;
    const int warp_m = (w >> 1) * 32;
    const int warp_n = (w & 1) * 64;
    const int nhalf = w & 1;

    float acc[2][8][4];
#pragma unroll
    for (int i = 0; i < 2; i++)
#pragma unroll
        for (int j = 0; j < 8; j++)
#pragma unroll
            for (int q = 0; q < 4; q++) acc[i][j][q] = 0.f;

    const int ar = tid >> 1;
    const int ac = (tid & 1) * 16;
    const int gr = block_row + ar;
    const bool valid = gr < N_NODES;
    const float* arow = A + (size_t)gr * F_IN + ac;

    // prologue: prefetch A tile k0=0 into registers
    float4 a_pre[4];
#pragma unroll
    for (int j = 0; j < 4; j++)
        a_pre[j] = valid ? *(const float4*)(arow + j * 4) : make_float4(0.f, 0.f, 0.f, 0.f);

    for (int k0 = 0; k0 < F_IN; k0 += 32) {
        // convert prefetched A regs -> smem (hi/lo split)
#pragma unroll
        for (int j = 0; j < 4; j++) {
            float xs[4] = {a_pre[j].x, a_pre[j].y, a_pre[j].z, a_pre[j].w};
            __nv_bfloat16 hi[4], lo[4];
#pragma unroll
            for (int c = 0; c < 4; c++) {
                hi[c] = __float2bfloat16(xs[c]);
                lo[c] = __float2bfloat16(xs[c] - __bfloat162float(hi[c]));
            }
            __nv_bfloat162* ph = (__nv_bfloat162*)&As_hi[ar][ac + j * 4];
            __nv_bfloat162* pl = (__nv_bfloat162*)&As_lo[ar][ac + j * 4];
            ph[0] = __nv_bfloat162(hi[0], hi[1]);
            ph[1] = __nv_bfloat162(hi[2], hi[3]);
            pl[0] = __nv_bfloat162(lo[0], lo[1]);
            pl[1] = __nv_bfloat162(lo[2], lo[3]);
        }
        // B tile (L2-resident device array)
        {
            const __nv_bfloat16* bh = g_Bt_hi + (size_t)ar * F_IN + k0 + ac;
            const __nv_bfloat16* bl = g_Bt_lo + (size_t)ar * F_IN + k0 + ac;
            *(uint4*)&Bs_hi[ar][ac] = *(const uint4*)bh;
            *(uint4*)&Bs_hi[ar][ac + 8] = *(const uint4*)(bh + 8);
            *(uint4*)&Bs_lo[ar][ac] = *(const uint4*)bl;
            *(uint4*)&Bs_lo[ar][ac + 8] = *(const uint4*)(bl + 8);
        }
        __syncthreads();

        // prefetch NEXT A tile (DRAM latency hides under MMA phase below)
        if (k0 + 32 < F_IN) {
#pragma unroll
            for (int j = 0; j < 4; j++)
                a_pre[j] = valid ? *(const float4*)(arow + k0 + 32 + j * 4)
                                 : make_float4(0.f, 0.f, 0.f, 0.f);
        }

#pragma unroll
        for (int ks = 0; ks < 32; ks += 16) {
            const int fr = l >> 2;
            const int fc = ks + (l & 3) * 2;
            uint32_t ah[2][4], al[2][4];
#pragma unroll
            for (int mf = 0; mf < 2; mf++) {
                int r = warp_m + mf * 16 + fr;
                ah[mf][0] = *(const uint32_t*)&As_hi[r][fc];
                ah[mf][1] = *(const uint32_t*)&As_hi[r + 8][fc];
                ah[mf][2] = *(const uint32_t*)&As_hi[r][fc + 8];
                ah[mf][3] = *(const uint32_t*)&As_hi[r + 8][fc + 8];
                al[mf][0] = *(const uint32_t*)&As_lo[r][fc];
                al[mf][1] = *(const uint32_t*)&As_lo[r + 8][fc];
                al[mf][2] = *(const uint32_t*)&As_lo[r][fc + 8];
                al[mf][3] = *(const uint32_t*)&As_lo[r + 8][fc + 8];
            }
#pragma unroll
            for (int nf = 0; nf < 8; nf++) {
                int n = warp_n + nf * 8 + fr;
                uint32_t bh0 = *(const uint32_t*)&Bs_hi[n][fc];
                uint32_t bh1 = *(const uint32_t*)&Bs_hi[n][fc + 8];
                uint32_t bl0 = *(const uint32_t*)&Bs_lo[n][fc];
                uint32_t bl1 = *(const uint32_t*)&Bs_lo[n][fc + 8];
#pragma unroll
                for (int mf = 0; mf < 2; mf++) {
                    mma16816(acc[mf][nf], ah[mf][0], ah[mf][1], ah[mf][2], ah[mf][3], bh0, bh1);
                    mma16816(acc[mf][nf], ah[mf][0], ah[mf][1], ah[mf][2], ah[mf][3], bl0, bl1);
                    mma16816(acc[mf][nf], al[mf][0], al[mf][1], al[mf][2], al[mf][3], bh0, bh1);
                }
            }
        }
        __syncthreads();
    }

    const int fr = l >> 2;
    const int quad = l & 3;

#pragma unroll
    for (int mf = 0; mf < 2; mf++) {
        int rl0 = warp_m + mf * 16 + fr;
        int rl1 = rl0 + 8;
        int r0 = block_row + rl0;
        int r1 = block_row + rl1;
        float es0 = 0.f, ed0 = 0.f, es1 = 0.f, ed1 = 0.f;
#pragma unroll
        for (int nf = 0; nf < 8; nf++) {
            int cc = warp_n + nf * 8 + quad * 2;
            float as0 = a1_src[cc], as1 = a1_src[cc + 1];
            float ad0 = a1_dst[cc], ad1 = a1_dst[cc + 1];
            es0 += acc[mf][nf][0] * as0 + acc[mf][nf][1] * as1;
            ed0 += acc[mf][nf][0] * ad0 + acc[mf][nf][1] * ad1;
            es1 += acc[mf][nf][2] * as0 + acc[mf][nf][3] * as1;
            ed1 += acc[mf][nf][2] * ad0 + acc[mf][nf][3] * ad1;
            if (r0 < N_NODES) {
                __half2 hv = __floats2half2_rn(acc[mf][nf][0], acc[mf][nf][1]);
                g_h16[(size_t)r0 * (F_HID / 2) + (cc >> 1)] = *(uint32_t*)&hv;
            }
            if (r1 < N_NODES) {
                __half2 hv = __floats2half2_rn(acc[mf][nf][2], acc[mf][nf][3]);
                g_h16[(size_t)r1 * (F_HID / 2) + (cc >> 1)] = *(uint32_t*)&hv;
            }
        }
#pragma unroll
        for (int o = 1; o <= 2; o <<= 1) {
            es0 += __shfl_xor_sync(0xffffffffu, es0, o);
            ed0 += __shfl_xor_sync(0xffffffffu, ed0, o);
            es1 += __shfl_xor_sync(0xffffffffu, es1, o);
            ed1 += __shfl_xor_sync(0xffffffffu, ed1, o);
        }
        if (quad == 0) {
            es_s[rl0][nhalf] = es0;
            ed_s[rl0][nhalf] = ed0;
            es_s[rl1][nhalf] = es1;
            ed_s[rl1][nhalf] = ed1;
        }
    }
    __syncthreads();
    if (tid < 128) {
        int grr = block_row + tid;
        if (grr < N_NODES) {
            g_es1[grr] = es_s[tid][0] + es_s[tid][1];
            g_ed1[grr] = ed_s[tid][0] + ed_s[tid][1];
        }
    }
}

__device__ __forceinline__ float leaky(float x) { return x > 0.f ? x : 0.2f * x; }

// ---------------- edge-parallel weight precompute, layer 1 ----------------
__global__ void w1_pre_k() {
    int j = blockIdx.x * blockDim.x + threadIdx.x;
    if (j < N_EDGES) {
        int s = g_csr_src[j];
        int d = g_csr_dst[j];
        g_w1[j] = expf(leaky(g_es1[s] + g_ed1[d]));
    }
}

// ---------------- layer-1 aggregation: TWO nodes per warp, 2x2 interleave (R11 best) ----------------
__global__ __launch_bounds__(256) void agg1_k(const float* __restrict__ Wmu,
                                              const float* __restrict__ amus,
                                              const float* __restrict__ amud) {
    int warp = (blockIdx.x * blockDim.x + threadIdx.x) >> 5;
    int lane = threadIdx.x & 31;
    if (warp >= N_NODES / 2) return;
    int v0 = warp * 2, v1 = v0 + 1;
    int b0 = g_off[v0], e0 = g_off[v0 + 1];
    int e1 = g_off[v1 + 1];
    int b1 = e0;

    float A00 = 0.f, A01 = 0.f, A02 = 0.f, A03 = 0.f, D0 = 0.f;
    float A10 = 0.f, A11 = 0.f, A12 = 0.f, A13 = 0.f, D1 = 0.f;

    int j0 = b0, j1 = b1;
    while (j0 + 2 <= e0 && j1 + 2 <= e1) {
        int s00 = g_csr_src[j0], s01 = g_csr_src[j0 + 1];
        int s10 = g_csr_src[j1], s11 = g_csr_src[j1 + 1];
        float w00 = g_w1[j0], w01 = g_w1[j0 + 1];
        float w10 = g_w1[j1], w11 = g_w1[j1 + 1];
        const uint32_t* p00 = g_h16 + (size_t)s00 * (F_HID / 2);
        const uint32_t* p01 = g_h16 + (size_t)s01 * (F_HID / 2);
        const uint32_t* p10 = g_h16 + (size_t)s10 * (F_HID / 2);
        const uint32_t* p11 = g_h16 + (size_t)s11 * (F_HID / 2);
        uint32_t q00a = p00[lane], q00b = p00[lane + 32];
        uint32_t q01a = p01[lane], q01b = p01[lane + 32];
        uint32_t q10a = p10[lane], q10b = p10[lane + 32];
        uint32_t q11a = p11[lane], q11b = p11[lane + 32];
        float2 x00a = __half22float2(*(__half2*)&q00a), x00b = __half22float2(*(__half2*)&q00b);
        float2 x01a = __half22float2(*(__half2*)&q01a), x01b = __half22float2(*(__half2*)&q01b);
        float2 x10a = __half22float2(*(__half2*)&q10a), x10b = __half22float2(*(__half2*)&q10b);
        float2 x11a = __half22float2(*(__half2*)&q11a), x11b = __half22float2(*(__half2*)&q11b);
        D0 += w00 + w01;
        A00 += w00 * x00a.x + w01 * x01a.x;
        A01 += w00 * x00a.y + w01 * x01a.y;
        A02 += w00 * x00b.x + w01 * x01b.x;
        A03 += w00 * x00b.y + w01 * x01b.y;
        D1 += w10 + w11;
        A10 += w10 * x10a.x + w11 * x11a.x;
        A11 += w10 * x10a.y + w11 * x11a.y;
        A12 += w10 * x10b.x + w11 * x11b.x;
        A13 += w10 * x10b.y + w11 * x11b.y;
        j0 += 2;
        j1 += 2;
    }
    for (; j0 < e0; j0++) {
        int s = g_csr_src[j0];
        float wg = g_w1[j0];
        const uint32_t* p = g_h16 + (size_t)s * (F_HID / 2);
        uint32_t qa = p[lane], qb = p[lane + 32];
        float2 xa = __half22float2(*(__half2*)&qa), xb = __half22float2(*(__half2*)&qb);
        D0 += wg;
        A00 += wg * xa.x;
        A01 += wg * xa.y;
        A02 += wg * xb.x;
        A03 += wg * xb.y;
    }
    for (; j1 < e1; j1++) {
        int s = g_csr_src[j1];
        float wg = g_w1[j1];
        const uint32_t* p = g_h16 + (size_t)s * (F_HID / 2);
        uint32_t qa = p[lane], qb = p[lane + 32];
        float2 xa = __half22float2(*(__half2*)&qa), xb = __half22float2(*(__half2*)&qb);
        D1 += wg;
        A10 += wg * xa.x;
        A11 += wg * xa.y;
        A12 += wg * xb.x;
        A13 += wg * xb.y;
    }

    int f0 = 2 * lane, f1 = 2 * lane + 1, f2 = 64 + 2 * lane, f3 = 64 + 2 * lane + 1;
    float Wm00 = Wmu[f0 * 2], Wm01 = Wmu[f0 * 2 + 1];
    float Wm10 = Wmu[f1 * 2], Wm11 = Wmu[f1 * 2 + 1];
    float Wm20 = Wmu[f2 * 2], Wm21 = Wmu[f2 * 2 + 1];
    float Wm30 = Wmu[f3 * 2], Wm31 = Wmu[f3 * 2 + 1];

    float h00 = 0.f, h01 = 0.f, h10 = 0.f, h11 = 0.f;
    if (b0 < e0) {
        float inv = 1.f / fmaxf(D0, 1e-16f);
        float a0 = fmaxf(A00 * inv, 0.f), a1 = fmaxf(A01 * inv, 0.f);
        float a2 = fmaxf(A02 * inv, 0.f), a3 = fmaxf(A03 * inv, 0.f);
        h00 = a0 * Wm00 + a1 * Wm10 + a2 * Wm20 + a3 * Wm30;
        h01 = a0 * Wm01 + a1 * Wm11 + a2 * Wm21 + a3 * Wm31;
    }
    if (b1 < e1) {
        float inv = 1.f / fmaxf(D1, 1e-16f);
        float a0 = fmaxf(A10 * inv, 0.f), a1 = fmaxf(A11 * inv, 0.f);
        float a2 = fmaxf(A12 * inv, 0.f), a3 = fmaxf(A13 * inv, 0.f);
        h10 = a0 * Wm00 + a1 * Wm10 + a2 * Wm20 + a3 * Wm30;
        h11 = a0 * Wm01 + a1 * Wm11 + a2 * Wm21 + a3 * Wm31;
    }
#pragma unroll
    for (int o = 16; o; o >>= 1) {
        h00 += __shfl_xor_sync(0xffffffffu, h00, o);
        h01 += __shfl_xor_sync(0xffffffffu, h01, o);
        h10 += __shfl_xor_sync(0xffffffffu, h10, o);
        h11 += __shfl_xor_sync(0xffffffffu, h11, o);
    }
    if (lane == 0) {
        float as0 = amus[0], as1 = amus[1], ad0 = amud[0], ad1 = amud[1];
        g_h2e[v0] = make_float4(h00, h01, h00 * as0 + h01 * as1, h00 * ad0 + h01 * ad1);
        g_h2e[v1] = make_float4(h10, h11, h10 * as0 + h11 * as1, h10 * ad0 + h11 * ad1);
    }
}

// ---------------- layer-2 aggregation + logits: TWO nodes per warp, inline weights ----------------
__global__ __launch_bounds__(256) void agg2_logits_k(const int* __restrict__ input_y,
                                                     const float* __restrict__ ssw,
                                                     const float* __restrict__ ssb,
                                                     float* __restrict__ out,
                                                     float* __restrict__ mu_out) {
    __shared__ float sw0[N_SAMP], sw1[N_SAMP], sb[N_SAMP];
    for (int i = threadIdx.x; i < N_SAMP / 4; i += blockDim.x) {
        *(float4*)&sw0[i * 4] = *(const float4*)&g_sw0[i * 4];
        *(float4*)&sw1[i * 4] = *(const float4*)&g_sw1[i * 4];
        *(float4*)&sb[i * 4]  = *(const float4*)&g_sb[i * 4];
    }
    __syncthreads();

    int warp = (blockIdx.x * blockDim.x + threadIdx.x) >> 5;
    int lane = threadIdx.x & 31;
    if (warp >= N_NODES / 2) return;
    int v0 = warp * 2, v1 = v0 + 1;
    int b0 = g_off[v0], e0 = g_off[v0 + 1];
    int e1 = g_off[v1 + 1];
    int b1 = e0;
    float edv0 = g_h2e[v0].w;
    float edv1 = g_h2e[v1].w;

    float d0 = 0.f, a00 = 0.f, a01 = 0.f;
    float d1 = 0.f, a10 = 0.f, a11 = 0.f;
    int j0 = b0 + lane, j1 = b1 + lane;
    while (j0 < e0 && j1 < e1) {
        int s0 = g_csr_src[j0];
        int s1 = g_csr_src[j1];
        float4 he0 = g_h2e[s0];
        float4 he1 = g_h2e[s1];
        float w0 = expf(leaky(he0.z + edv0));
        float w1 = expf(leaky(he1.z + edv1));
        d0 += w0; a00 += w0 * he0.x; a01 += w0 * he0.y;
        d1 += w1; a10 += w1 * he1.x; a11 += w1 * he1.y;
        j0 += 32; j1 += 32;
    }
    for (; j0 < e0; j0 += 32) {
        int s = g_csr_src[j0];
        float4 he = g_h2e[s];
        float w = expf(leaky(he.z + edv0));
        d0 += w; a00 += w * he.x; a01 += w * he.y;
    }
    for (; j1 < e1; j1 += 32) {
        int s = g_csr_src[j1];
        float4 he = g_h2e[s];
        float w = expf(leaky(he.z + edv1));
        d1 += w; a10 += w * he.x; a11 += w * he.y;
    }
#pragma unroll
    for (int o = 16; o; o >>= 1) {
        d0  += __shfl_xor_sync(0xffffffffu, d0, o);
        a00 += __shfl_xor_sync(0xffffffffu, a00, o);
        a01 += __shfl_xor_sync(0xffffffffu, a01, o);
        d1  += __shfl_xor_sync(0xffffffffu, d1, o);
        a10 += __shfl_xor_sync(0xffffffffu, a10, o);
        a11 += __shfl_xor_sync(0xffffffffu, a11, o);
    }
    float mu00 = 0.f, mu01 = 0.f, mu10 = 0.f, mu11 = 0.f;
    if (b0 < e0) {
        float inv = 1.f / fmaxf(d0, 1e-16f);
        mu00 = a00 * inv; mu01 = a01 * inv;
    }
    if (b1 < e1) {
        float inv = 1.f / fmaxf(d1, 1e-16f);
        mu10 = a10 * inv; mu11 = a11 * inv;
    }

    float* row0 = out + (size_t)v0 * (N_SAMP + 1);
    float* row1 = out + (size_t)v1 * (N_SAMP + 1);
    if (lane == 0) {
        mu_out[2 * v0] = mu00; mu_out[2 * v0 + 1] = mu01;
        mu_out[2 * v1] = mu10; mu_out[2 * v1 + 1] = mu11;
        int y0 = input_y[v0];
        int y1 = input_y[v1];
        __stcs(&row0[0], mu00 * ssw[2 * y0] + mu01 * ssw[2 * y0 + 1] + ssb[y0]);
        __stcs(&row1[0], mu10 * ssw[2 * y1] + mu11 * ssw[2 * y1 + 1] + ssb[y1]);
    }
    for (int c = lane + 1; c <= N_SAMP; c += 32) {
        int s = c - 1;
        float b = sb[s], s0v = sw0[s], s1v = sw1[s];
        __stcs(&row0[c], mu00 * s0v + mu01 * s1v + b);
        __stcs(&row1[c], mu10 * s0v + mu11 * s1v + b);
    }
}

// ---------------- launch (fork/join: CSR chain overlaps prep+GEMM) ----------------
static cudaStream_t g_s2 = nullptr;
static cudaEvent_t g_ev_fork = nullptr;
static cudaEvent_t g_ev_join = nullptr;

extern "C" void kernel_launch(void* const* d_in, const int* in_sizes, int n_in,
                              void* d_out, int out_size) {
    const float* X         = (const float*)d_in[0];
    const int*   input_y   = (const int*)d_in[2];
    const int*   edge_idx  = (const int*)d_in[3];
    const int*   sample_ids= (const int*)d_in[4];
    const float* W1        = (const float*)d_in[5];
    const float* a1_src    = (const float*)d_in[6];
    const float* a1_dst    = (const float*)d_in[7];
    const float* W_mu      = (const float*)d_in[8];
    const float* amu_src   = (const float*)d_in[9];
    const float* amu_dst   = (const float*)d_in[10];
    const float* ss_weight = (const float*)d_in[14];
    const float* ss_bias   = (const float*)d_in[15];
    float* out = (float*)d_out;

    float* mu_out = out + (size_t)N_NODES * (N_SAMP + 1);

    if (g_s2 == nullptr) {
        cudaStreamCreateWithFlags(&g_s2, cudaStreamNonBlocking);
        cudaEventCreateWithFlags(&g_ev_fork, cudaEventDisableTiming);
        cudaEventCreateWithFlags(&g_ev_join, cudaEventDisableTiming);
    }

    // fork immediately: CSR chain on s2, prep+GEMM on main
    cudaEventRecord(g_ev_fork, 0);
    cudaStreamWaitEvent(g_s2, g_ev_fork, 0);
    zero_counts_k<<<(N_NODES + 255) / 256, 256, 0, g_s2>>>();
    hist_k<<<(N_EDGES / 4 + 255) / 256, 256, 0, g_s2>>>(edge_idx);
    bsum_k<<<SCAN_NB, SCAN_B, 0, g_s2>>>();
    scan_bsums_k<<<1, 512, 0, g_s2>>>();
    write_off_k<<<SCAN_NB, SCAN_B, 0, g_s2>>>();
    fill_k<<<(N_EDGES / 4 + 255) / 256, 256, 0, g_s2>>>(edge_idx);
    cudaEventRecord(g_ev_join, g_s2);

    // main stream: W split + sample gather, then pipelined tensor-core GEMM
    prep_k<<<(F_HID * F_IN + 255) / 256, 256>>>(W1, sample_ids, ss_weight, ss_bias);
    gemm_mma_k<<<(N_NODES + 127) / 128, 256>>>(X, a1_src, a1_dst);

    // join, then w1 precompute + aggregation phases
    cudaStreamWaitEvent(0, g_ev_join, 0);
    int edge_blocks = (N_EDGES + 255) / 256;
    int pair_blocks = ((N_NODES / 2) * 32 + 255) / 256;   // 6250
    w1_pre_k<<<edge_blocks, 256>>>();
    agg1_k<<<pair_blocks, 256>>>(W_mu, amu_src, amu_dst);
    agg2_logits_k<<<pair_blocks, 256>>>(input_y, ss_weight, ss_bias, out, mu_out);
}

// round 16
// speedup vs baseline: 1.0799x; 1.0088x over previous
#include <cuda_runtime.h>
#include <cuda_bf16.h>
#include <cuda_fp16.h>
#include <math.h>
#include <stdint.h>

#define N_NODES 100000
#define N_EDGES 1600000
#define F_IN 256
#define F_HID 128
#define VOCAB 100000
#define N_SAMP 512

#define SCAN_B 256
#define SCAN_NB ((N_NODES + SCAN_B - 1) / SCAN_B)   // 391

// ---------------- scratch (static __device__ — no allocations) ----------------
__device__ uint32_t g_h16[(size_t)N_NODES * (F_HID / 2)];   // h as half2 pairs, 25.6 MB
__device__ float g_es1[N_NODES];
__device__ float g_ed1[N_NODES];
__device__ int   g_counts[N_NODES];
__device__ int   g_off[N_NODES + 1];
__device__ int   g_cursor[N_NODES];
__device__ int   g_csr_src[N_EDGES];
__device__ int   g_csr_dst[N_EDGES];
__device__ float g_w1[N_EDGES];
__device__ float4 g_h2e[N_NODES];           // {h2_0, h2_1, es2, ed2}
__device__ int   g_bsum[SCAN_NB];
__device__ int   g_boff[SCAN_NB];
__device__ __nv_bfloat16 g_Bt_hi[F_HID * F_IN];
__device__ __nv_bfloat16 g_Bt_lo[F_HID * F_IN];
__device__ float g_sw0[N_SAMP];
__device__ float g_sw1[N_SAMP];
__device__ float g_sb[N_SAMP];

// ---------------- s2 branch: zero counts ----------------
__global__ void zero_counts_k() {
    int i = blockIdx.x * blockDim.x + threadIdx.x;
    if (i < N_NODES) g_counts[i] = 0;
}

// ---------------- main branch: W1 split + sample-table gather ----------------
__global__ void prep_k(const float* __restrict__ W1,
                       const int* __restrict__ sample_ids,
                       const float* __restrict__ ssw,
                       const float* __restrict__ ssb) {
    int i = blockIdx.x * blockDim.x + threadIdx.x;
    if (i < F_HID * F_IN) {
        int n = i / F_IN;
        int k = i % F_IN;
        float w = W1[(size_t)k * F_HID + n];
        __nv_bfloat16 hi = __float2bfloat16(w);
        float r = w - __bfloat162float(hi);
        g_Bt_hi[i] = hi;
        g_Bt_lo[i] = __float2bfloat16(r);
    }
    if (i < N_SAMP) {
        int sid = sample_ids[i];
        g_sw0[i] = ssw[2 * sid];
        g_sw1[i] = ssw[2 * sid + 1];
        g_sb[i] = ssb[sid];
    }
}

// ---------------- CSR build (vectorized 4 edges/thread) ----------------
__global__ void hist_k(const int* __restrict__ edge_index) {
    int t = blockIdx.x * blockDim.x + threadIdx.x;
    int e = t * 4;
    if (e < N_EDGES) {
        int4 d = *(const int4*)(edge_index + N_EDGES + e);
        atomicAdd(&g_counts[d.x], 1);
        atomicAdd(&g_counts[d.y], 1);
        atomicAdd(&g_counts[d.z], 1);
        atomicAdd(&g_counts[d.w], 1);
    }
}

__global__ __launch_bounds__(SCAN_B) void bsum_k() {
    int i = blockIdx.x * SCAN_B + threadIdx.x;
    int c = (i < N_NODES) ? g_counts[i] : 0;
#pragma unroll
    for (int o = 16; o; o >>= 1) c += __shfl_xor_sync(0xffffffffu, c, o);
    __shared__ int ws[SCAN_B / 32];
    if ((threadIdx.x & 31) == 0) ws[threadIdx.x >> 5] = c;
    __syncthreads();
    if (threadIdx.x < SCAN_B / 32) {
        int v = ws[threadIdx.x];
#pragma unroll
        for (int o = SCAN_B / 64; o; o >>= 1) v += __shfl_xor_sync(0xffffffffu, v, o);
        if (threadIdx.x == 0) g_bsum[blockIdx.x] = v;
    }
}

__global__ __launch_bounds__(512) void scan_bsums_k() {
    __shared__ int s[512];
    int t = threadIdx.x;
    int v = (t < SCAN_NB) ? g_bsum[t] : 0;
    s[t] = v;
    __syncthreads();
    for (int d = 1; d < 512; d <<= 1) {
        int x = 0;
        if (t >= d) x = s[t - d];
        __syncthreads();
        s[t] += x;
        __syncthreads();
    }
    if (t < SCAN_NB) g_boff[t] = s[t] - v;
    if (t == 511) g_off[N_NODES] = s[SCAN_NB - 1];
}

__global__ __launch_bounds__(SCAN_B) void write_off_k() {
    int i = blockIdx.x * SCAN_B + threadIdx.x;
    int lane = threadIdx.x & 31;
    int wid = threadIdx.x >> 5;
    int c = (i < N_NODES) ? g_counts[i] : 0;
    int inc = c;
#pragma unroll
    for (int d = 1; d < 32; d <<= 1) {
        int x = __shfl_up_sync(0xffffffffu, inc, d);
        if (lane >= d) inc += x;
    }
    __shared__ int wsum[SCAN_B / 32];
    if (lane == 31) wsum[wid] = inc;
    __syncthreads();
    if (threadIdx.x == 0) {
        int run = 0;
#pragma unroll
        for (int wv = 0; wv < SCAN_B / 32; wv++) {
            int x = wsum[wv];
            wsum[wv] = run;
            run += x;
        }
    }
    __syncthreads();
    int off = g_boff[blockIdx.x] + wsum[wid] + inc - c;
    if (i < N_NODES) {
        g_off[i] = off;
        g_cursor[i] = off;
    }
}

__global__ void fill_k(const int* __restrict__ edge_index) {
    int t = blockIdx.x * blockDim.x + threadIdx.x;
    int e = t * 4;
    if (e < N_EDGES) {
        int4 s = *(const int4*)(edge_index + e);
        int4 d = *(const int4*)(edge_index + N_EDGES + e);
        int p0 = atomicAdd(&g_cursor[d.x], 1);
        g_csr_src[p0] = s.x; g_csr_dst[p0] = d.x;
        int p1 = atomicAdd(&g_cursor[d.y], 1);
        g_csr_src[p1] = s.y; g_csr_dst[p1] = d.y;
        int p2 = atomicAdd(&g_cursor[d.z], 1);
        g_csr_src[p2] = s.z; g_csr_dst[p2] = d.z;
        int p3 = atomicAdd(&g_cursor[d.w], 1);
        g_csr_src[p3] = s.w; g_csr_dst[p3] = d.w;
    }
}

// ---------------- tensor-core GEMM: double-buffered smem + A reg-prefetch ----------------
#define SMEM_STRIDE 40
#define ARR_ELEMS (128 * SMEM_STRIDE)    // 5120 bf16 per array
#define STAGE_ELEMS (4 * ARR_ELEMS)      // 20480 bf16 per stage
#define GEMM_SMEM_BYTES (2 * STAGE_ELEMS * 2)  // 81920 B

__device__ __forceinline__ void mma16816(float* d,
                                         uint32_t a0, uint32_t a1, uint32_t a2, uint32_t a3,
                                         uint32_t b0, uint32_t b1) {
    asm volatile(
        "mma.sync.aligned.m16n8k16.row.col.f32.bf16.bf16.f32 "
        "{%0,%1,%2,%3}, {%4,%5,%6,%7}, {%8,%9}, {%0,%1,%2,%3};\n"
        : "+f"(d[0]), "+f"(d[1]), "+f"(d[2]), "+f"(d[3])
        : "r"(a0), "r"(a1), "r"(a2), "r"(a3), "r"(b0), "r"(b1));
}

__global__ __launch_bounds__(256) void gemm_mma_k(const float* __restrict__ A,
                                                  const float* __restrict__ a1_src,
                                                  const float* __restrict__ a1_dst) {
    extern __shared__ __nv_bfloat16 smem_dyn[];
    __shared__ float es_s[128][2], ed_s[128][2];

    const int tid = threadIdx.x;
    const int block_row = blockIdx.x * 128;
    const int w = tid >> 5, l = tid & 31;
    const int warp_m = (w >> 1) * 32;
    const int warp_n = (w & 1) * 64;
    const int nhalf = w & 1;

    float acc[2][8][4];
#pragma unroll
    for (int i = 0; i < 2; i++)
#pragma unroll
        for (int j = 0; j < 8; j++)
#pragma unroll
            for (int q = 0; q < 4; q++) acc[i][j][q] = 0.f;

    const int ar = tid >> 1;
    const int ac = (tid & 1) * 16;
    const int gr = block_row + ar;
    const bool valid = gr < N_NODES;
    const float* arow = A + (size_t)gr * F_IN + ac;

    // helper lambdas via macros over dynamic smem
#define AS_HI(st) (smem_dyn + (st) * STAGE_ELEMS)
#define AS_LO(st) (smem_dyn + (st) * STAGE_ELEMS + ARR_ELEMS)
#define BS_HI(st) (smem_dyn + (st) * STAGE_ELEMS + 2 * ARR_ELEMS)
#define BS_LO(st) (smem_dyn + (st) * STAGE_ELEMS + 3 * ARR_ELEMS)

    const int NT = F_IN / 32;   // 8 k-tiles

    // prologue: load A tile 0, fill stage 0
    float4 a_pre[4];
#pragma unroll
    for (int j = 0; j < 4; j++)
        a_pre[j] = valid ? *(const float4*)(arow + j * 4) : make_float4(0.f, 0.f, 0.f, 0.f);
    {
#pragma unroll
        for (int j = 0; j < 4; j++) {
            float xs[4] = {a_pre[j].x, a_pre[j].y, a_pre[j].z, a_pre[j].w};
            __nv_bfloat16 hi[4], lo[4];
#pragma unroll
            for (int c = 0; c < 4; c++) {
                hi[c] = __float2bfloat16(xs[c]);
                lo[c] = __float2bfloat16(xs[c] - __bfloat162float(hi[c]));
            }
            __nv_bfloat162* ph = (__nv_bfloat162*)(AS_HI(0) + ar * SMEM_STRIDE + ac + j * 4);
            __nv_bfloat162* pl = (__nv_bfloat162*)(AS_LO(0) + ar * SMEM_STRIDE + ac + j * 4);
            ph[0] = __nv_bfloat162(hi[0], hi[1]);
            ph[1] = __nv_bfloat162(hi[2], hi[3]);
            pl[0] = __nv_bfloat162(lo[0], lo[1]);
            pl[1] = __nv_bfloat162(lo[2], lo[3]);
        }
        const __nv_bfloat16* bh = g_Bt_hi + (size_t)ar * F_IN + ac;
        const __nv_bfloat16* bl = g_Bt_lo + (size_t)ar * F_IN + ac;
        *(uint4*)(BS_HI(0) + ar * SMEM_STRIDE + ac) = *(const uint4*)bh;
        *(uint4*)(BS_HI(0) + ar * SMEM_STRIDE + ac + 8) = *(const uint4*)(bh + 8);
        *(uint4*)(BS_LO(0) + ar * SMEM_STRIDE + ac) = *(const uint4*)bl;
        *(uint4*)(BS_LO(0) + ar * SMEM_STRIDE + ac + 8) = *(const uint4*)(bl + 8);
    }
    // prefetch A tile 1
    if (NT > 1) {
#pragma unroll
        for (int j = 0; j < 4; j++)
            a_pre[j] = valid ? *(const float4*)(arow + 32 + j * 4) : make_float4(0.f, 0.f, 0.f, 0.f);
    }
    __syncthreads();

    for (int it = 0; it < NT; it++) {
        const int stage = it & 1;
        const int nstage = stage ^ 1;
        // stage it+1: cvt prefetched A regs + load B (independent of MMA on current stage)
        if (it + 1 < NT) {
#pragma unroll
            for (int j = 0; j < 4; j++) {
                float xs[4] = {a_pre[j].x, a_pre[j].y, a_pre[j].z, a_pre[j].w};
                __nv_bfloat16 hi[4], lo[4];
#pragma unroll
                for (int c = 0; c < 4; c++) {
                    hi[c] = __float2bfloat16(xs[c]);
                    lo[c] = __float2bfloat16(xs[c] - __bfloat162float(hi[c]));
                }
                __nv_bfloat162* ph = (__nv_bfloat162*)(AS_HI(nstage) + ar * SMEM_STRIDE + ac + j * 4);
                __nv_bfloat162* pl = (__nv_bfloat162*)(AS_LO(nstage) + ar * SMEM_STRIDE + ac + j * 4);
                ph[0] = __nv_bfloat162(hi[0], hi[1]);
                ph[1] = __nv_bfloat162(hi[2], hi[3]);
                pl[0] = __nv_bfloat162(lo[0], lo[1]);
                pl[1] = __nv_bfloat162(lo[2], lo[3]);
            }
            int kn = (it + 1) * 32;
            const __nv_bfloat16* bh = g_Bt_hi + (size_t)ar * F_IN + kn + ac;
            const __nv_bfloat16* bl = g_Bt_lo + (size_t)ar * F_IN + kn + ac;
            *(uint4*)(BS_HI(nstage) + ar * SMEM_STRIDE + ac) = *(const uint4*)bh;
            *(uint4*)(BS_HI(nstage) + ar * SMEM_STRIDE + ac + 8) = *(const uint4*)(bh + 8);
            *(uint4*)(BS_LO(nstage) + ar * SMEM_STRIDE + ac) = *(const uint4*)bl;
            *(uint4*)(BS_LO(nstage) + ar * SMEM_STRIDE + ac + 8) = *(const uint4*)(bl + 8);
        }
        // prefetch A tile it+2 (hidden under MMA below)
        if (it + 2 < NT) {
            int kn2 = (it + 2) * 32;
#pragma unroll
            for (int j = 0; j < 4; j++)
                a_pre[j] = valid ? *(const float4*)(arow + kn2 + j * 4) : make_float4(0.f, 0.f, 0.f, 0.f);
        }

        // MMA over current stage
        const __nv_bfloat16* ash = AS_HI(stage);
        const __nv_bfloat16* asl = AS_LO(stage);
        const __nv_bfloat16* bsh = BS_HI(stage);
        const __nv_bfloat16* bsl = BS_LO(stage);
#pragma unroll
        for (int ks = 0; ks < 32; ks += 16) {
            const int fr = l >> 2;
            const int fc = ks + (l & 3) * 2;
            uint32_t ah[2][4], al[2][4];
#pragma unroll
            for (int mf = 0; mf < 2; mf++) {
                int r = warp_m + mf * 16 + fr;
                ah[mf][0] = *(const uint32_t*)(ash + r * SMEM_STRIDE + fc);
                ah[mf][1] = *(const uint32_t*)(ash + (r + 8) * SMEM_STRIDE + fc);
                ah[mf][2] = *(const uint32_t*)(ash + r * SMEM_STRIDE + fc + 8);
                ah[mf][3] = *(const uint32_t*)(ash + (r + 8) * SMEM_STRIDE + fc + 8);
                al[mf][0] = *(const uint32_t*)(asl + r * SMEM_STRIDE + fc);
                al[mf][1] = *(const uint32_t*)(asl + (r + 8) * SMEM_STRIDE + fc);
                al[mf][2] = *(const uint32_t*)(asl + r * SMEM_STRIDE + fc + 8);
                al[mf][3] = *(const uint32_t*)(asl + (r + 8) * SMEM_STRIDE + fc + 8);
            }
#pragma unroll
            for (int nf = 0; nf < 8; nf++) {
                int n = warp_n + nf * 8 + fr;
                uint32_t bh0 = *(const uint32_t*)(bsh + n * SMEM_STRIDE + fc);
                uint32_t bh1 = *(const uint32_t*)(bsh + n * SMEM_STRIDE + fc + 8);
                uint32_t bl0 = *(const uint32_t*)(bsl + n * SMEM_STRIDE + fc);
                uint32_t bl1 = *(const uint32_t*)(bsl + n * SMEM_STRIDE + fc + 8);
#pragma unroll
                for (int mf = 0; mf < 2; mf++) {
                    mma16816(acc[mf][nf], ah[mf][0], ah[mf][1], ah[mf][2], ah[mf][3], bh0, bh1);
                    mma16816(acc[mf][nf], ah[mf][0], ah[mf][1], ah[mf][2], ah[mf][3], bl0, bl1);
                    mma16816(acc[mf][nf], al[mf][0], al[mf][1], al[mf][2], al[mf][3], bh0, bh1);
                }
            }
        }
        __syncthreads();
    }

    const int fr = l >> 2;
    const int quad = l & 3;

#pragma unroll
    for (int mf = 0; mf < 2; mf++) {
        int rl0 = warp_m + mf * 16 + fr;
        int rl1 = rl0 + 8;
        int r0 = block_row + rl0;
        int r1 = block_row + rl1;
        float es0 = 0.f, ed0 = 0.f, es1 = 0.f, ed1 = 0.f;
#pragma unroll
        for (int nf = 0; nf < 8; nf++) {
            int cc = warp_n + nf * 8 + quad * 2;
            float as0 = a1_src[cc], as1 = a1_src[cc + 1];
            float ad0 = a1_dst[cc], ad1 = a1_dst[cc + 1];
            es0 += acc[mf][nf][0] * as0 + acc[mf][nf][1] * as1;
            ed0 += acc[mf][nf][0] * ad0 + acc[mf][nf][1] * ad1;
            es1 += acc[mf][nf][2] * as0 + acc[mf][nf][3] * as1;
            ed1 += acc[mf][nf][2] * ad0 + acc[mf][nf][3] * ad1;
            if (r0 < N_NODES) {
                __half2 hv = __floats2half2_rn(acc[mf][nf][0], acc[mf][nf][1]);
                g_h16[(size_t)r0 * (F_HID / 2) + (cc >> 1)] = *(uint32_t*)&hv;
            }
            if (r1 < N_NODES) {
                __half2 hv = __floats2half2_rn(acc[mf][nf][2], acc[mf][nf][3]);
                g_h16[(size_t)r1 * (F_HID / 2) + (cc >> 1)] = *(uint32_t*)&hv;
            }
        }
#pragma unroll
        for (int o = 1; o <= 2; o <<= 1) {
            es0 += __shfl_xor_sync(0xffffffffu, es0, o);
            ed0 += __shfl_xor_sync(0xffffffffu, ed0, o);
            es1 += __shfl_xor_sync(0xffffffffu, es1, o);
            ed1 += __shfl_xor_sync(0xffffffffu, ed1, o);
        }
        if (quad == 0) {
            es_s[rl0][nhalf] = es0;
            ed_s[rl0][nhalf] = ed0;
            es_s[rl1][nhalf] = es1;
            ed_s[rl1][nhalf] = ed1;
        }
    }
    __syncthreads();
    if (tid < 128) {
        int grr = block_row + tid;
        if (grr < N_NODES) {
            g_es1[grr] = es_s[tid][0] + es_s[tid][1];
            g_ed1[grr] = ed_s[tid][0] + ed_s[tid][1];
        }
    }
}

__device__ __forceinline__ float leaky(float x) { return x > 0.f ? x : 0.2f * x; }

// ---------------- edge-parallel weight precompute, layer 1 ----------------
__global__ void w1_pre_k() {
    int j = blockIdx.x * blockDim.x + threadIdx.x;
    if (j < N_EDGES) {
        int s = g_csr_src[j];
        int d = g_csr_dst[j];
        g_w1[j] = expf(leaky(g_es1[s] + g_ed1[d]));
    }
}

// ---------------- layer-1 aggregation: TWO nodes per warp, 2x2 interleave ----------------
__global__ __launch_bounds__(256) void agg1_k(const float* __restrict__ Wmu,
                                              const float* __restrict__ amus,
                                              const float* __restrict__ amud) {
    int warp = (blockIdx.x * blockDim.x + threadIdx.x) >> 5;
    int lane = threadIdx.x & 31;
    if (warp >= N_NODES / 2) return;
    int v0 = warp * 2, v1 = v0 + 1;
    int b0 = g_off[v0], e0 = g_off[v0 + 1];
    int e1 = g_off[v1 + 1];
    int b1 = e0;

    float A00 = 0.f, A01 = 0.f, A02 = 0.f, A03 = 0.f, D0 = 0.f;
    float A10 = 0.f, A11 = 0.f, A12 = 0.f, A13 = 0.f, D1 = 0.f;

    int j0 = b0, j1 = b1;
    while (j0 + 2 <= e0 && j1 + 2 <= e1) {
        int s00 = g_csr_src[j0], s01 = g_csr_src[j0 + 1];
        int s10 = g_csr_src[j1], s11 = g_csr_src[j1 + 1];
        float w00 = g_w1[j0], w01 = g_w1[j0 + 1];
        float w10 = g_w1[j1], w11 = g_w1[j1 + 1];
        const uint32_t* p00 = g_h16 + (size_t)s00 * (F_HID / 2);
        const uint32_t* p01 = g_h16 + (size_t)s01 * (F_HID / 2);
        const uint32_t* p10 = g_h16 + (size_t)s10 * (F_HID / 2);
        const uint32_t* p11 = g_h16 + (size_t)s11 * (F_HID / 2);
        uint32_t q00a = p00[lane], q00b = p00[lane + 32];
        uint32_t q01a = p01[lane], q01b = p01[lane + 32];
        uint32_t q10a = p10[lane], q10b = p10[lane + 32];
        uint32_t q11a = p11[lane], q11b = p11[lane + 32];
        float2 x00a = __half22float2(*(__half2*)&q00a), x00b = __half22float2(*(__half2*)&q00b);
        float2 x01a = __half22float2(*(__half2*)&q01a), x01b = __half22float2(*(__half2*)&q01b);
        float2 x10a = __half22float2(*(__half2*)&q10a), x10b = __half22float2(*(__half2*)&q10b);
        float2 x11a = __half22float2(*(__half2*)&q11a), x11b = __half22float2(*(__half2*)&q11b);
        D0 += w00 + w01;
        A00 += w00 * x00a.x + w01 * x01a.x;
        A01 += w00 * x00a.y + w01 * x01a.y;
        A02 += w00 * x00b.x + w01 * x01b.x;
        A03 += w00 * x00b.y + w01 * x01b.y;
        D1 += w10 + w11;
        A10 += w10 * x10a.x + w11 * x11a.x;
        A11 += w10 * x10a.y + w11 * x11a.y;
        A12 += w10 * x10b.x + w11 * x11b.x;
        A13 += w10 * x10b.y + w11 * x11b.y;
        j0 += 2;
        j1 += 2;
    }
    for (; j0 < e0; j0++) {
        int s = g_csr_src[j0];
        float wg = g_w1[j0];
        const uint32_t* p = g_h16 + (size_t)s * (F_HID / 2);
        uint32_t qa = p[lane], qb = p[lane + 32];
        float2 xa = __half22float2(*(__half2*)&qa), xb = __half22float2(*(__half2*)&qb);
        D0 += wg;
        A00 += wg * xa.x;
        A01 += wg * xa.y;
        A02 += wg * xb.x;
        A03 += wg * xb.y;
    }
    for (; j1 < e1; j1++) {
        int s = g_csr_src[j1];
        float wg = g_w1[j1];
        const uint32_t* p = g_h16 + (size_t)s * (F_HID / 2);
        uint32_t qa = p[lane], qb = p[lane + 32];
        float2 xa = __half22float2(*(__half2*)&qa), xb = __half22float2(*(__half2*)&qb);
        D1 += wg;
        A10 += wg * xa.x;
        A11 += wg * xa.y;
        A12 += wg * xb.x;
        A13 += wg * xb.y;
    }

    int f0 = 2 * lane, f1 = 2 * lane + 1, f2 = 64 + 2 * lane, f3 = 64 + 2 * lane + 1;
    float Wm00 = Wmu[f0 * 2], Wm01 = Wmu[f0 * 2 + 1];
    float Wm10 = Wmu[f1 * 2], Wm11 = Wmu[f1 * 2 + 1];
    float Wm20 = Wmu[f2 * 2], Wm21 = Wmu[f2 * 2 + 1];
    float Wm30 = Wmu[f3 * 2], Wm31 = Wmu[f3 * 2 + 1];

    float h00 = 0.f, h01 = 0.f, h10 = 0.f, h11 = 0.f;
    if (b0 < e0) {
        float inv = 1.f / fmaxf(D0, 1e-16f);
        float a0 = fmaxf(A00 * inv, 0.f), a1 = fmaxf(A01 * inv, 0.f);
        float a2 = fmaxf(A02 * inv, 0.f), a3 = fmaxf(A03 * inv, 0.f);
        h00 = a0 * Wm00 + a1 * Wm10 + a2 * Wm20 + a3 * Wm30;
        h01 = a0 * Wm01 + a1 * Wm11 + a2 * Wm21 + a3 * Wm31;
    }
    if (b1 < e1) {
        float inv = 1.f / fmaxf(D1, 1e-16f);
        float a0 = fmaxf(A10 * inv, 0.f), a1 = fmaxf(A11 * inv, 0.f);
        float a2 = fmaxf(A12 * inv, 0.f), a3 = fmaxf(A13 * inv, 0.f);
        h10 = a0 * Wm00 + a1 * Wm10 + a2 * Wm20 + a3 * Wm30;
        h11 = a0 * Wm01 + a1 * Wm11 + a2 * Wm21 + a3 * Wm31;
    }
#pragma unroll
    for (int o = 16; o; o >>= 1) {
        h00 += __shfl_xor_sync(0xffffffffu, h00, o);
        h01 += __shfl_xor_sync(0xffffffffu, h01, o);
        h10 += __shfl_xor_sync(0xffffffffu, h10, o);
        h11 += __shfl_xor_sync(0xffffffffu, h11, o);
    }
    if (lane == 0) {
        float as0 = amus[0], as1 = amus[1], ad0 = amud[0], ad1 = amud[1];
        g_h2e[v0] = make_float4(h00, h01, h00 * as0 + h01 * as1, h00 * ad0 + h01 * ad1);
        g_h2e[v1] = make_float4(h10, h11, h10 * as0 + h11 * as1, h10 * ad0 + h11 * ad1);
    }
}

// ---------------- layer-2 aggregation + logits: TWO nodes per warp, inline weights ----------------
__global__ __launch_bounds__(256) void agg2_logits_k(const int* __restrict__ input_y,
                                                     const float* __restrict__ ssw,
                                                     const float* __restrict__ ssb,
                                                     float* __restrict__ out,
                                                     float* __restrict__ mu_out) {
    __shared__ float sw0[N_SAMP], sw1[N_SAMP], sb[N_SAMP];
    for (int i = threadIdx.x; i < N_SAMP / 4; i += blockDim.x) {
        *(float4*)&sw0[i * 4] = *(const float4*)&g_sw0[i * 4];
        *(float4*)&sw1[i * 4] = *(const float4*)&g_sw1[i * 4];
        *(float4*)&sb[i * 4]  = *(const float4*)&g_sb[i * 4];
    }
    __syncthreads();

    int warp = (blockIdx.x * blockDim.x + threadIdx.x) >> 5;
    int lane = threadIdx.x & 31;
    if (warp >= N_NODES / 2) return;
    int v0 = warp * 2, v1 = v0 + 1;
    int b0 = g_off[v0], e0 = g_off[v0 + 1];
    int e1 = g_off[v1 + 1];
    int b1 = e0;
    float edv0 = g_h2e[v0].w;
    float edv1 = g_h2e[v1].w;

    float d0 = 0.f, a00 = 0.f, a01 = 0.f;
    float d1 = 0.f, a10 = 0.f, a11 = 0.f;
    int j0 = b0 + lane, j1 = b1 + lane;
    while (j0 < e0 && j1 < e1) {
        int s0 = g_csr_src[j0];
        int s1 = g_csr_src[j1];
        float4 he0 = g_h2e[s0];
        float4 he1 = g_h2e[s1];
        float w0 = expf(leaky(he0.z + edv0));
        float w1 = expf(leaky(he1.z + edv1));
        d0 += w0; a00 += w0 * he0.x; a01 += w0 * he0.y;
        d1 += w1; a10 += w1 * he1.x; a11 += w1 * he1.y;
        j0 += 32; j1 += 32;
    }
    for (; j0 < e0; j0 += 32) {
        int s = g_csr_src[j0];
        float4 he = g_h2e[s];
        float w = expf(leaky(he.z + edv0));
        d0 += w; a00 += w * he.x; a01 += w * he.y;
    }
    for (; j1 < e1; j1 += 32) {
        int s = g_csr_src[j1];
        float4 he = g_h2e[s];
        float w = expf(leaky(he.z + edv1));
        d1 += w; a10 += w * he.x; a11 += w * he.y;
    }
#pragma unroll
    for (int o = 16; o; o >>= 1) {
        d0  += __shfl_xor_sync(0xffffffffu, d0, o);
        a00 += __shfl_xor_sync(0xffffffffu, a00, o);
        a01 += __shfl_xor_sync(0xffffffffu, a01, o);
        d1  += __shfl_xor_sync(0xffffffffu, d1, o);
        a10 += __shfl_xor_sync(0xffffffffu, a10, o);
        a11 += __shfl_xor_sync(0xffffffffu, a11, o);
    }
    float mu00 = 0.f, mu01 = 0.f, mu10 = 0.f, mu11 = 0.f;
    if (b0 < e0) {
        float inv = 1.f / fmaxf(d0, 1e-16f);
        mu00 = a00 * inv; mu01 = a01 * inv;
    }
    if (b1 < e1) {
        float inv = 1.f / fmaxf(d1, 1e-16f);
        mu10 = a10 * inv; mu11 = a11 * inv;
    }

    float* row0 = out + (size_t)v0 * (N_SAMP + 1);
    float* row1 = out + (size_t)v1 * (N_SAMP + 1);
    if (lane == 0) {
        mu_out[2 * v0] = mu00; mu_out[2 * v0 + 1] = mu01;
        mu_out[2 * v1] = mu10; mu_out[2 * v1 + 1] = mu11;
        int y0 = input_y[v0];
        int y1 = input_y[v1];
        __stcs(&row0[0], mu00 * ssw[2 * y0] + mu01 * ssw[2 * y0 + 1] + ssb[y0]);
        __stcs(&row1[0], mu10 * ssw[2 * y1] + mu11 * ssw[2 * y1 + 1] + ssb[y1]);
    }
    for (int c = lane + 1; c <= N_SAMP; c += 32) {
        int s = c - 1;
        float b = sb[s], s0v = sw0[s], s1v = sw1[s];
        __stcs(&row0[c], mu00 * s0v + mu01 * s1v + b);
        __stcs(&row1[c], mu10 * s0v + mu11 * s1v + b);
    }
}

// ---------------- launch (fork/join: CSR chain overlaps prep+GEMM) ----------------
static cudaStream_t g_s2 = nullptr;
static cudaEvent_t g_ev_fork = nullptr;
static cudaEvent_t g_ev_join = nullptr;

extern "C" void kernel_launch(void* const* d_in, const int* in_sizes, int n_in,
                              void* d_out, int out_size) {
    const float* X         = (const float*)d_in[0];
    const int*   input_y   = (const int*)d_in[2];
    const int*   edge_idx  = (const int*)d_in[3];
    const int*   sample_ids= (const int*)d_in[4];
    const float* W1        = (const float*)d_in[5];
    const float* a1_src    = (const float*)d_in[6];
    const float* a1_dst    = (const float*)d_in[7];
    const float* W_mu      = (const float*)d_in[8];
    const float* amu_src   = (const float*)d_in[9];
    const float* amu_dst   = (const float*)d_in[10];
    const float* ss_weight = (const float*)d_in[14];
    const float* ss_bias   = (const float*)d_in[15];
    float* out = (float*)d_out;

    float* mu_out = out + (size_t)N_NODES * (N_SAMP + 1);

    if (g_s2 == nullptr) {
        cudaStreamCreateWithFlags(&g_s2, cudaStreamNonBlocking);
        cudaEventCreateWithFlags(&g_ev_fork, cudaEventDisableTiming);
        cudaEventCreateWithFlags(&g_ev_join, cudaEventDisableTiming);
        cudaFuncSetAttribute(gemm_mma_k, cudaFuncAttributeMaxDynamicSharedMemorySize,
                             GEMM_SMEM_BYTES);
    }

    // fork immediately: CSR chain on s2, prep+GEMM on main
    cudaEventRecord(g_ev_fork, 0);
    cudaStreamWaitEvent(g_s2, g_ev_fork, 0);
    zero_counts_k<<<(N_NODES + 255) / 256, 256, 0, g_s2>>>();
    hist_k<<<(N_EDGES / 4 + 255) / 256, 256, 0, g_s2>>>(edge_idx);
    bsum_k<<<SCAN_NB, SCAN_B, 0, g_s2>>>();
    scan_bsums_k<<<1, 512, 0, g_s2>>>();
    write_off_k<<<SCAN_NB, SCAN_B, 0, g_s2>>>();
    fill_k<<<(N_EDGES / 4 + 255) / 256, 256, 0, g_s2>>>(edge_idx);
    cudaEventRecord(g_ev_join, g_s2);

    // main stream: W split + sample gather, then double-buffered tensor-core GEMM
    prep_k<<<(F_HID * F_IN + 255) / 256, 256>>>(W1, sample_ids, ss_weight, ss_bias);
    gemm_mma_k<<<(N_NODES + 127) / 128, 256, GEMM_SMEM_BYTES>>>(X, a1_src, a1_dst);

    // join, then w1 precompute + aggregation phases
    cudaStreamWaitEvent(0, g_ev_join, 0);
    int edge_blocks = (N_EDGES + 255) / 256;
    int pair_blocks = ((N_NODES / 2) * 32 + 255) / 256;   // 6250
    w1_pre_k<<<edge_blocks, 256>>>();
    agg1_k<<<pair_blocks, 256>>>(W_mu, amu_src, amu_dst);
    agg2_logits_k<<<pair_blocks, 256>>>(input_y, ss_weight, ss_bias, out, mu_out);
}